// round 6
// baseline (speedup 1.0000x reference)
#include <cuda_runtime.h>
#include <math.h>

// Problem dims (fixed by the reference)
#define BATCH 8
#define CHN   128
#define HWX   16384                 // 128*128
#define CHW   (CHN*HWX)             // 2097152
#define NPT   (BATCH*CHW)           // 16777216 elements per tensor

// ---------------------------------------------------------------------------
// Scratch (static device globals: allocation-free per harness rules)
// ---------------------------------------------------------------------------
__device__ float d_tmp[6][NPT];        // conv1x1 outputs (pre-depthwise)
__device__ float d_qkv[6][NPT];        // Qi,Ki,Vi,Qw,Kw,Vw after depthwise
__device__ float d_att[2][NPT];        // Aw (0), Ai (1)
__device__ float d_outlin[NPT];        // final linear output (p-major, co contiguous)
__device__ float d_mean[2][BATCH*HWX];
__device__ float d_rstd[2][BATCH*HWX];
__device__ float d_Wg[6][CHN*CHN];     // conv weights * gamma
__device__ float d_Ssum[6][CHN];       // row sums of Wg
__device__ float d_probs[2][BATCH*CHN*CHN];   // softmax(a1), softmax(a2)
__device__ float d_partial[256][CHN*CHN];     // QK split-K partials (16 slabs * 16 z)

struct PtrArgs {
    const float* f[2];      // F_i, F_w
    const float* g[2];      // g1, g2
    const float* w[6];      // qw1,kw1,vw1,qw2,kw2,vw2
    const float* bias[6];   // conv biases
};

// ---------------------------------------------------------------------------
// K0: Wg = W * g, Ssum = row sums of Wg.  grid: 6*128 blocks of 128 threads
// ---------------------------------------------------------------------------
__global__ void k_prep(PtrArgs pa) {
    int t = blockIdx.x >> 7;
    int o = blockIdx.x & 127;
    int c = threadIdx.x;
    const float* gsrc = pa.g[t < 3 ? 0 : 1];
    float v = pa.w[t][o * CHN + c] * gsrc[c];
    d_Wg[t][o * CHN + c] = v;
    float s = v;
    #pragma unroll
    for (int off = 16; off; off >>= 1) s += __shfl_xor_sync(0xffffffffu, s, off);
    __shared__ float sm[4];
    if ((c & 31) == 0) sm[c >> 5] = s;
    __syncthreads();
    if (c == 0) d_Ssum[t][o] = sm[0] + sm[1] + sm[2] + sm[3];
}

// ---------------------------------------------------------------------------
// K1: LayerNorm statistics per pixel.  grid: (B*HW/256, 2), block 256
// ---------------------------------------------------------------------------
__global__ void k_ln(PtrArgs pa) {
    int s = blockIdx.y;
    int p = blockIdx.x * 256 + threadIdx.x;          // 0 .. B*HW-1
    int b = p >> 14;
    int hw = p & 16383;
    const float* x = pa.f[s] + (size_t)b * CHW + hw;
    float s1 = 0.f, s2 = 0.f;
    #pragma unroll 16
    for (int c = 0; c < CHN; c++) {
        float v = x[(size_t)c * HWX];
        s1 += v;
        s2 += v * v;
    }
    float m = s1 * (1.0f / CHN);
    float var = s2 * (1.0f / CHN) - m * m;
    d_mean[s][p] = m;
    d_rstd[s][p] = rsqrtf(var + 1e-5f);
}

// ---------------------------------------------------------------------------
// K2 / K6: generic M=128,K=128 GEMM over N=HW columns (k-row stride HW).
// MODE 0: fused-LN conv1x1  (A = Wg[t], X = raw input, epilogue LN + bias)
// MODE 1: AV                (A = probs, X = V buffer, raw epilogue)
// grid: (HW/128, nz), block 256, thread tile 8x8
// ---------------------------------------------------------------------------
template <int MODE>
__global__ void __launch_bounds__(256) k_gemm(PtrArgs pa) {
    const int z = blockIdx.y;
    const int t = z >> 3;
    const int b = z & 7;
    const int n0 = blockIdx.x << 7;

    const float* A;
    const float* X;
    float* Y;
    const float* meanp = nullptr;
    const float* rstdp = nullptr;
    const float* Sp = nullptr;
    const float* biasp = nullptr;

    if (MODE == 0) {
        A = d_Wg[t];
        int s = (t < 3) ? 0 : 1;
        X = pa.f[s] + (size_t)b * CHW;
        Y = d_tmp[t] + (size_t)b * CHW;
        meanp = d_mean[s] + b * HWX;
        rstdp = d_rstd[s] + b * HWX;
        Sp = d_Ssum[t];
        biasp = pa.bias[t];
    } else {
        A = d_probs[t] + b * (CHN * CHN);
        X = d_qkv[t == 0 ? 5 : 2] + (size_t)b * CHW;   // a1@Vw, a2@Vi
        Y = d_att[t] + (size_t)b * CHW;
    }

    __shared__ float Ws[16][129];
    __shared__ float Xs[16][128];
    const int tid = threadIdx.x;
    const int tm = (tid >> 4) << 3;
    const int tn = (tid & 15) << 3;

    float acc[8][8];
    #pragma unroll
    for (int i = 0; i < 8; i++)
        #pragma unroll
        for (int j = 0; j < 8; j++) acc[i][j] = 0.f;

    for (int k0 = 0; k0 < CHN; k0 += 16) {
        #pragma unroll
        for (int i = 0; i < 8; i++) {
            int id = tid + (i << 8);
            Ws[id & 15][id >> 4] = A[(id >> 4) * CHN + k0 + (id & 15)];
        }
        #pragma unroll
        for (int i = 0; i < 2; i++) {
            int id = tid + (i << 8);
            int kk = id >> 5, col = (id & 31) << 2;
            *(float4*)&Xs[kk][col] =
                *(const float4*)(X + (size_t)(k0 + kk) * HWX + n0 + col);
        }
        __syncthreads();
        #pragma unroll
        for (int kk = 0; kk < 16; kk++) {
            float av[8], bv[8];
            #pragma unroll
            for (int i = 0; i < 8; i++) av[i] = Ws[kk][tm + i];
            #pragma unroll
            for (int j = 0; j < 8; j++) bv[j] = Xs[kk][tn + j];
            #pragma unroll
            for (int i = 0; i < 8; i++)
                #pragma unroll
                for (int j = 0; j < 8; j++)
                    acc[i][j] = fmaf(av[i], bv[j], acc[i][j]);
        }
        __syncthreads();
    }

    if (MODE == 0) {
        float rs[8], ms[8];
        #pragma unroll
        for (int j = 0; j < 8; j++) {
            rs[j] = rstdp[n0 + tn + j];
            ms[j] = meanp[n0 + tn + j] * rs[j];
        }
        #pragma unroll
        for (int i = 0; i < 8; i++) {
            float Sv = Sp[tm + i];
            float bb = biasp[tm + i];
            float o[8];
            #pragma unroll
            for (int j = 0; j < 8; j++)
                o[j] = fmaf(acc[i][j], rs[j], fmaf(-Sv, ms[j], bb));
            float* yp = Y + (size_t)(tm + i) * HWX + n0 + tn;
            *(float4*)yp       = make_float4(o[0], o[1], o[2], o[3]);
            *(float4*)(yp + 4) = make_float4(o[4], o[5], o[6], o[7]);
        }
    } else {
        #pragma unroll
        for (int i = 0; i < 8; i++) {
            float* yp = Y + (size_t)(tm + i) * HWX + n0 + tn;
            *(float4*)yp       = make_float4(acc[i][0], acc[i][1], acc[i][2], acc[i][3]);
            *(float4*)(yp + 4) = make_float4(acc[i][4], acc[i][5], acc[i][6], acc[i][7]);
        }
    }
}

// ---------------------------------------------------------------------------
// K3: depthwise 3x3, SAME padding. grid (W/32, H/8, B*C), block (32,8)
// ---------------------------------------------------------------------------
__global__ void k_dw(int t, const float* wd, const float* bd) {
    int z = blockIdx.z;                 // b*C + c  (matches plane offset z*HW)
    int c = z & 127;
    __shared__ float w9[9];
    __shared__ float bsh;
    if (threadIdx.y == 0 && threadIdx.x < 9) w9[threadIdx.x] = wd[c * 9 + threadIdx.x];
    if (threadIdx.y == 0 && threadIdx.x == 9) bsh = bd[c];
    __syncthreads();

    int wx = blockIdx.x * 32 + threadIdx.x;
    int hy = blockIdx.y * 8 + threadIdx.y;
    const float* sp = d_tmp[t] + (size_t)z * HWX;
    float acc = bsh;
    #pragma unroll
    for (int i = 0; i < 3; i++) {
        int hh = hy - 1 + i;
        if ((unsigned)hh < 128u) {
            #pragma unroll
            for (int j = 0; j < 3; j++) {
                int ww = wx - 1 + j;
                if ((unsigned)ww < 128u)
                    acc = fmaf(w9[i * 3 + j], sp[hh * 128 + ww], acc);
            }
        }
    }
    d_qkv[t][(size_t)z * HWX + hy * 128 + wx] = acc;
}

// ---------------------------------------------------------------------------
// K4: QK logits, split-K.  C = M^T N on (16384,128) row-major buffers.
// grid (16 slabs, 16 z={gq,b}), block 256, thread tile 8x8, slab K=1024.
// ---------------------------------------------------------------------------
__global__ void __launch_bounds__(256) k_qk() {
    const int slab = blockIdx.x;
    const int z = blockIdx.y;
    const int gq = z >> 3, b = z & 7;
    const float* Qb = d_qkv[gq == 0 ? 0 : 3] + (size_t)b * CHW;  // Qi / Qw
    const float* Kb = d_qkv[gq == 0 ? 4 : 1] + (size_t)b * CHW;  // Kw / Ki
    float* P = d_partial[z * 16 + slab];

    __shared__ float Qs[16][128];
    __shared__ float Ks[16][128];
    const int tid = threadIdx.x;
    const int tm = (tid >> 4) << 3;
    const int tn = (tid & 15) << 3;

    float acc[8][8];
    #pragma unroll
    for (int i = 0; i < 8; i++)
        #pragma unroll
        for (int j = 0; j < 8; j++) acc[i][j] = 0.f;

    const int kb = slab << 10;
    for (int k0 = 0; k0 < 1024; k0 += 16) {
        #pragma unroll
        for (int i = 0; i < 2; i++) {
            int id = tid + (i << 8);
            int kk = id >> 5, col = (id & 31) << 2;
            size_t roff = (size_t)(kb + k0 + kk) * 128 + col;
            *(float4*)&Qs[kk][col] = *(const float4*)(Qb + roff);
            *(float4*)&Ks[kk][col] = *(const float4*)(Kb + roff);
        }
        __syncthreads();
        #pragma unroll
        for (int kk = 0; kk < 16; kk++) {
            float av[8], bv[8];
            #pragma unroll
            for (int i = 0; i < 8; i++) av[i] = Qs[kk][tm + i];
            #pragma unroll
            for (int j = 0; j < 8; j++) bv[j] = Ks[kk][tn + j];
            #pragma unroll
            for (int i = 0; i < 8; i++)
                #pragma unroll
                for (int j = 0; j < 8; j++)
                    acc[i][j] = fmaf(av[i], bv[j], acc[i][j]);
        }
        __syncthreads();
    }
    #pragma unroll
    for (int i = 0; i < 8; i++) {
        float* pp = P + (tm + i) * 128 + tn;
        *(float4*)pp       = make_float4(acc[i][0], acc[i][1], acc[i][2], acc[i][3]);
        *(float4*)(pp + 4) = make_float4(acc[i][4], acc[i][5], acc[i][6], acc[i][7]);
    }
}

// ---------------------------------------------------------------------------
// K5: reduce split-K partials + row softmax. grid 2048 rows, block 128
// ---------------------------------------------------------------------------
__global__ void k_softmax() {
    int r = blockIdx.x;               // 0..2047
    int gq = r >> 10;
    int rb = r & 1023;
    int b = rb >> 7;
    int cc = rb & 127;
    int d = threadIdx.x;

    const float* pf = &d_partial[0][0];
    size_t base = (size_t)((gq * 8 + b) * 16) * (CHN * CHN) + cc * 128 + d;
    float v = 0.f;
    #pragma unroll
    for (int s = 0; s < 16; s++) v += pf[base + (size_t)s * (CHN * CHN)];

    __shared__ float sm[4];
    __shared__ float ss[4];
    int lane = d & 31, wid = d >> 5;
    float m = v;
    #pragma unroll
    for (int off = 16; off; off >>= 1) m = fmaxf(m, __shfl_xor_sync(0xffffffffu, m, off));
    if (lane == 0) sm[wid] = m;
    __syncthreads();
    m = fmaxf(fmaxf(sm[0], sm[1]), fmaxf(sm[2], sm[3]));

    float e = expf(v - m);
    float sum = e;
    #pragma unroll
    for (int off = 16; off; off >>= 1) sum += __shfl_xor_sync(0xffffffffu, sum, off);
    if (lane == 0) ss[wid] = sum;
    __syncthreads();
    sum = ss[0] + ss[1] + ss[2] + ss[3];

    d_probs[gq][(b * 128 + cc) * 128 + d] = e / sum;
}

// ---------------------------------------------------------------------------
// K7: final linear. out_lin[p,co] = sum_k lw[co,k] * cat[p,k], cat rows are
// contiguous 128-chunks of d_att buffers. grid (HW/128, 8), block 256.
// ---------------------------------------------------------------------------
__global__ void __launch_bounds__(256) k_final(const float* lw, const float* lb) {
    const int b = blockIdx.y;
    const int p0 = blockIdx.x << 7;
    const float* A0 = d_att[0] + (size_t)b * CHW;
    const float* A1 = d_att[1] + (size_t)b * CHW;

    __shared__ float Ws[16][129];
    __shared__ float Xs[16][129];
    const int tid = threadIdx.x;
    const int tm = (tid >> 4) << 3;   // co
    const int tn = (tid & 15) << 3;   // p (local)

    float acc[8][8];
    #pragma unroll
    for (int i = 0; i < 8; i++)
        #pragma unroll
        for (int j = 0; j < 8; j++) acc[i][j] = 0.f;

    for (int k0 = 0; k0 < 256; k0 += 16) {
        const float* Xb = (k0 < 128) ? A0 : A1;
        int kq = k0 & 127;
        #pragma unroll
        for (int i = 0; i < 8; i++) {
            int id = tid + (i << 8);
            int co = id >> 4, kk = id & 15;
            Ws[kk][co] = lw[co * 256 + k0 + kk];
        }
        #pragma unroll
        for (int i = 0; i < 8; i++) {
            int id = tid + (i << 8);
            int pp = id >> 4, kk = id & 15;
            Xs[kk][pp] = Xb[(size_t)(p0 + pp) * 128 + kq + kk];
        }
        __syncthreads();
        #pragma unroll
        for (int kk = 0; kk < 16; kk++) {
            float av[8], xv[8];
            #pragma unroll
            for (int i = 0; i < 8; i++) av[i] = Ws[kk][tm + i];
            #pragma unroll
            for (int j = 0; j < 8; j++) xv[j] = Xs[kk][tn + j];
            #pragma unroll
            for (int i = 0; i < 8; i++)
                #pragma unroll
                for (int j = 0; j < 8; j++)
                    acc[i][j] = fmaf(av[i], xv[j], acc[i][j]);
        }
        __syncthreads();
    }

    float* OL = d_outlin + (size_t)b * CHW;
    #pragma unroll
    for (int j = 0; j < 8; j++) {
        float o[8];
        #pragma unroll
        for (int i = 0; i < 8; i++) o[i] = acc[i][j] + lb[tm + i];
        float* yp = OL + (size_t)(p0 + tn + j) * 128 + tm;
        *(float4*)yp       = make_float4(o[0], o[1], o[2], o[3]);
        *(float4*)(yp + 4) = make_float4(o[4], o[5], o[6], o[7]);
    }
}

// ---------------------------------------------------------------------------
// K8: output permutation + residual.
// out[b,c4,h4,w4] = out_lin[b, w4*128+c4, h4] + F_i + F_w
// grid (4,4,1024), block (32,8), smem-transpose, coalesced both sides.
// ---------------------------------------------------------------------------
__global__ void k_perm(const float* Fi, const float* Fw, float* out) {
    int z = blockIdx.z;             // b*128 + c4
    int b = z >> 7;
    int c4 = z & 127;
    int h0 = blockIdx.y * 32;
    int w0 = blockIdx.x * 32;
    __shared__ float s[32][33];
    int tx = threadIdx.x, ty = threadIdx.y;
    const float* OL = d_outlin + (size_t)b * CHW;

    #pragma unroll
    for (int it = 0; it < 4; it++) {
        int wr = ty + it * 8;       // local w4
        s[wr][tx] = OL[(size_t)((w0 + wr) * 128 + c4) * 128 + h0 + tx];
    }
    __syncthreads();
    #pragma unroll
    for (int it = 0; it < 4; it++) {
        int hl = ty + it * 8;       // local h4
        size_t idx = (size_t)(z * 128 + (h0 + hl)) * 128 + w0 + tx;
        out[idx] = s[tx][hl] + Fi[idx] + Fw[idx];
    }
}

// ---------------------------------------------------------------------------
// Launch.  Input ordering: the harness passes inputs in metadata.txt order,
// which follows setup_inputs() dict-insertion order:
//   0:F_i 1:F_w 2:g1 3:g2 4..9:qw1,kw1,vw1,qw2,kw2,vw2
//   10..15:qb1,kb1,vb1,qb2,kb2,vb2  16..21:qdw1..vdw2  22..27:qdb1..vdb2
//   28:lw 29:lb
// Guard on in_sizes[5] in case the order is reference-signature interleaved
// (qw1,qb1,kw1,kb1,...): size 128 at slot 5 => interleaved.
// ---------------------------------------------------------------------------
extern "C" void kernel_launch(void* const* d_in, const int* in_sizes, int n_in,
                              void* d_out, int out_size) {
    (void)n_in; (void)out_size;
    const float* F_i = (const float*)d_in[0];
    const float* F_w = (const float*)d_in[1];

    const bool interleaved = (in_sizes[5] == 128);

    PtrArgs pa;
    pa.f[0] = F_i;
    pa.f[1] = F_w;
    pa.g[0] = (const float*)d_in[2];
    pa.g[1] = (const float*)d_in[3];

    int w_idx[6], b_idx[6], dw_idx[6], db_idx[6];
    int lw_i, lb_i;
    if (interleaved) {
        for (int t = 0; t < 6; t++) {
            w_idx[t]  = 4 + 2 * t;
            b_idx[t]  = 5 + 2 * t;
            dw_idx[t] = 16 + 2 * t;
            db_idx[t] = 17 + 2 * t;
        }
        lw_i = 28; lb_i = 29;
    } else {
        for (int t = 0; t < 6; t++) {
            w_idx[t]  = 4 + t;       // qw1,kw1,vw1,qw2,kw2,vw2
            b_idx[t]  = 10 + t;      // qb1,kb1,vb1,qb2,kb2,vb2
            dw_idx[t] = 16 + t;      // qdw1,kdw1,vdw1,qdw2,kdw2,vdw2
            db_idx[t] = 22 + t;      // qdb1,kdb1,vdb1,qdb2,kdb2,vdb2
        }
        lw_i = 28; lb_i = 29;
    }
    for (int t = 0; t < 6; t++) {
        pa.w[t]    = (const float*)d_in[w_idx[t]];
        pa.bias[t] = (const float*)d_in[b_idx[t]];
    }

    // 0) weight*gamma + row sums
    k_prep<<<6 * 128, 128>>>(pa);
    // 1) LN stats
    k_ln<<<dim3(BATCH * HWX / 256, 2), 256>>>(pa);
    // 2) fused LN + 1x1 conv (6 tensors x 8 batches)
    k_gemm<0><<<dim3(HWX / 128, 48), 256>>>(pa);
    // 3) depthwise 3x3
    for (int t = 0; t < 6; t++)
        k_dw<<<dim3(4, 16, 1024), dim3(32, 8)>>>(t, (const float*)d_in[dw_idx[t]],
                                                 (const float*)d_in[db_idx[t]]);
    // 4) QK logits split-K
    k_qk<<<dim3(16, 16), 256>>>();
    // 5) reduce + softmax
    k_softmax<<<2048, 128>>>();
    // 6) AV GEMMs
    k_gemm<1><<<dim3(HWX / 128, 16), 256>>>(pa);
    // 7) final linear
    k_final<<<dim3(HWX / 128, BATCH), 256>>>((const float*)d_in[lw_i],
                                             (const float*)d_in[lb_i]);
    // 8) permutation + residual
    k_perm<<<dim3(4, 4, 1024), dim3(32, 8)>>>(F_i, F_w, (float*)d_out);
}

// round 9
// speedup vs baseline: 1.2690x; 1.2690x over previous
#include <cuda_runtime.h>
#include <cuda_bf16.h>
#include <math.h>
#include <stdint.h>

// Problem dims (fixed by the reference)
#define BATCH 8
#define CHN   128
#define HWX   16384                 // 128*128
#define CHW   (CHN*HWX)             // 2097152
#define NPT   (BATCH*CHW)           // 16777216 elements per tensor

// ---------------------------------------------------------------------------
// Scratch (static device globals: allocation-free per harness rules)
// ---------------------------------------------------------------------------
__device__ float d_tmp[6][NPT];        // conv1x1 outputs (pre-depthwise)
__device__ float d_qkv[6][NPT];        // Qi,Ki,Vi,Qw,Kw,Vw after depthwise
__device__ float d_att[2][NPT];        // Aw (0), Ai (1)
__device__ float d_outlin[NPT];        // final linear output
__device__ float d_mean[2][BATCH*HWX];
__device__ float d_rstd[2][BATCH*HWX];
__device__ float d_Wg[6][CHN*CHN];     // conv weights * gamma
__device__ float d_Ssum[6][CHN];       // row sums of Wg
__device__ float d_probs[2][BATCH*CHN*CHN];   // softmax(a1), softmax(a2)
__device__ float d_partial[256][CHN*CHN];     // QK split-K partials

struct PtrArgs {
    const float* f[2];      // F_i, F_w
    const float* g[2];      // g1, g2
    const float* w[6];      // qw1,kw1,vw1,qw2,kw2,vw2
    const float* bias[6];   // conv biases
};
struct DwArgs {
    const float* w[6];
    const float* b[6];
};

// ---------------------------------------------------------------------------
// Helpers (compute_103-safe: ldmatrix + mma.sync only, no tcgen05)
// ---------------------------------------------------------------------------
__device__ __forceinline__ uint32_t s2u(const void* p) {
    uint32_t r;
    asm("{ .reg .u64 t; cvta.to.shared.u64 t, %1; cvt.u32.u64 %0, t; }" : "=r"(r) : "l"(p));
    return r;
}
__device__ __forceinline__ uint32_t pack_bf16(float a, float b) {
    __nv_bfloat162 t = __floats2bfloat162_rn(a, b);   // .x = a (low), .y = b (high)
    return *(uint32_t*)&t;
}
__device__ __forceinline__ void ldsm4(uint32_t* r, uint32_t addr) {
    asm volatile("ldmatrix.sync.aligned.m8n8.x4.shared.b16 {%0,%1,%2,%3}, [%4];"
                 : "=r"(r[0]), "=r"(r[1]), "=r"(r[2]), "=r"(r[3]) : "r"(addr));
}
__device__ __forceinline__ void ldsm4t(uint32_t* r, uint32_t addr) {
    asm volatile("ldmatrix.sync.aligned.m8n8.x4.trans.shared.b16 {%0,%1,%2,%3}, [%4];"
                 : "=r"(r[0]), "=r"(r[1]), "=r"(r[2]), "=r"(r[3]) : "r"(addr));
}
__device__ __forceinline__ void mma16816(float* d, const uint32_t* a, const uint32_t* b) {
    asm volatile(
        "mma.sync.aligned.m16n8k16.row.col.f32.bf16.bf16.f32 "
        "{%0,%1,%2,%3}, {%4,%5,%6,%7}, {%8,%9}, {%0,%1,%2,%3};"
        : "+f"(d[0]), "+f"(d[1]), "+f"(d[2]), "+f"(d[3])
        : "r"(a[0]), "r"(a[1]), "r"(a[2]), "r"(a[3]), "r"(b[0]), "r"(b[1]));
}

// ---------------------------------------------------------------------------
// K0: Wg = W * g, Ssum = row sums of Wg.
// ---------------------------------------------------------------------------
__global__ void k_prep(PtrArgs pa) {
    int t = blockIdx.x >> 7;
    int o = blockIdx.x & 127;
    int c = threadIdx.x;
    const float* gsrc = pa.g[t < 3 ? 0 : 1];
    float v = pa.w[t][o * CHN + c] * gsrc[c];
    d_Wg[t][o * CHN + c] = v;
    float s = v;
    #pragma unroll
    for (int off = 16; off; off >>= 1) s += __shfl_xor_sync(0xffffffffu, s, off);
    __shared__ float sm[4];
    if ((c & 31) == 0) sm[c >> 5] = s;
    __syncthreads();
    if (c == 0) d_Ssum[t][o] = sm[0] + sm[1] + sm[2] + sm[3];
}

// ---------------------------------------------------------------------------
// K1: LayerNorm statistics per pixel.
// ---------------------------------------------------------------------------
__global__ void k_ln(PtrArgs pa) {
    int s = blockIdx.y;
    int p = blockIdx.x * 256 + threadIdx.x;
    int b = p >> 14;
    int hw = p & 16383;
    const float* x = pa.f[s] + (size_t)b * CHW + hw;
    float s1 = 0.f, s2 = 0.f;
    #pragma unroll 16
    for (int c = 0; c < CHN; c++) {
        float v = x[(size_t)c * HWX];
        s1 += v;
        s2 += v * v;
    }
    float m = s1 * (1.0f / CHN);
    float var = s2 * (1.0f / CHN) - m * m;
    d_mean[s][p] = m;
    d_rstd[s][p] = rsqrtf(var + 1e-5f);
}

// ---------------------------------------------------------------------------
// K_MMA: split-bf16 HMMA GEMM, M=128, K=128, N-tile=128 per CTA.
// MODE 0: fused-LN conv1x1 (A = Wg[t], X = raw input [k][n], LN epilogue)
// MODE 1: AV               (A = probs,  X = V buffer [k][n], raw epilogue)
// 256 threads = 8 warps (4 M x 2 N); warp tile 32x64; mma.m16n8k16 bf16.
// SMEM: A/X as hi/lo bf16, row stride 136 (ldmatrix bank-conflict-free).
// ---------------------------------------------------------------------------
#define PADK 136
#define SM_AH 1024
#define SM_AL 35840
#define SM_XH 70656
#define SM_XL 105472
#define SMTOT 140288

template <int MODE>
__global__ void __launch_bounds__(256, 1) k_mma(PtrArgs pa) {
    extern __shared__ char dynsm[];
    float* s_rs = (float*)dynsm;
    float* s_ms = (float*)(dynsm + 512);
    __nv_bfloat16* sAH = (__nv_bfloat16*)(dynsm + SM_AH);
    __nv_bfloat16* sAL = (__nv_bfloat16*)(dynsm + SM_AL);
    __nv_bfloat16* sXH = (__nv_bfloat16*)(dynsm + SM_XH);
    __nv_bfloat16* sXL = (__nv_bfloat16*)(dynsm + SM_XL);

    const int tid = threadIdx.x;
    const int z = blockIdx.x;
    const int n0 = blockIdx.y << 7;

    const float* A;
    const float* X;
    float* Y;
    const float *meanp = nullptr, *rstdp = nullptr, *Sp = nullptr, *biasp = nullptr;
    if (MODE == 0) {
        int t = z % 6, b = z / 6;         // t fast: 3 consecutive CTAs share X in L2
        int s = (t < 3) ? 0 : 1;
        A = d_Wg[t];
        X = pa.f[s] + (size_t)b * CHW;
        Y = d_tmp[t] + (size_t)b * CHW;
        meanp = d_mean[s] + b * HWX;
        rstdp = d_rstd[s] + b * HWX;
        Sp = d_Ssum[t];
        biasp = pa.bias[t];
    } else {
        int gq = z & 1, b = z >> 1;
        A = d_probs[gq] + b * (CHN * CHN);
        X = d_qkv[gq == 0 ? 5 : 2] + (size_t)b * CHW;   // a1@Vw, a2@Vi
        Y = d_att[gq] + (size_t)b * CHW;
    }

    // ---- fills: f32 -> hi/lo bf16 split, padded-stride smem ----
    #pragma unroll
    for (int it = 0; it < 16; it++) {
        int idx = tid + (it << 8);
        int m = idx >> 5, q = (idx & 31) << 2;
        float4 v = *(const float4*)(A + m * CHN + q);
        float h0 = __bfloat162float(__float2bfloat16(v.x));
        float h1 = __bfloat162float(__float2bfloat16(v.y));
        float h2 = __bfloat162float(__float2bfloat16(v.z));
        float h3 = __bfloat162float(__float2bfloat16(v.w));
        *(uint2*)(sAH + m * PADK + q) = make_uint2(pack_bf16(v.x, v.y), pack_bf16(v.z, v.w));
        *(uint2*)(sAL + m * PADK + q) = make_uint2(pack_bf16(v.x - h0, v.y - h1),
                                                   pack_bf16(v.z - h2, v.w - h3));
    }
    #pragma unroll
    for (int it = 0; it < 16; it++) {
        int idx = tid + (it << 8);
        int k = idx >> 5, q = (idx & 31) << 2;
        float4 v = *(const float4*)(X + (size_t)k * HWX + n0 + q);
        float h0 = __bfloat162float(__float2bfloat16(v.x));
        float h1 = __bfloat162float(__float2bfloat16(v.y));
        float h2 = __bfloat162float(__float2bfloat16(v.z));
        float h3 = __bfloat162float(__float2bfloat16(v.w));
        *(uint2*)(sXH + k * PADK + q) = make_uint2(pack_bf16(v.x, v.y), pack_bf16(v.z, v.w));
        *(uint2*)(sXL + k * PADK + q) = make_uint2(pack_bf16(v.x - h0, v.y - h1),
                                                   pack_bf16(v.z - h2, v.w - h3));
    }
    if (MODE == 0 && tid < 128) {
        float rv = rstdp[n0 + tid];
        s_rs[tid] = rv;
        s_ms[tid] = meanp[n0 + tid] * rv;
    }
    __syncthreads();

    // ---- mma mainloop ----
    const int wid = tid >> 5, lane = tid & 31;
    const int m0w = (wid >> 1) << 5;     // warp M offset (0,32,64,96)
    const int n0w = (wid & 1) << 6;      // warp N offset (0,64)
    const int tle = lane >> 3, li = lane & 7;
    const uint32_t smem0 = s2u(dynsm);
    // ldmatrix lane addresses (tile = lane>>3 ordering; a0..a3 / b0..b1 mapping)
    const uint32_t aoff = smem0 + SM_AH +
        (((uint32_t)(m0w + li + ((tle & 1) << 3)) * PADK + ((tle & 2) << 2)) << 1);
    const uint32_t boff = smem0 + SM_XH +
        ((((uint32_t)(li + ((tle & 1) << 3))) * PADK + (uint32_t)n0w + ((tle & 2) << 2)) << 1);
    const uint32_t DA = SM_AL - SM_AH;
    const uint32_t DB = SM_XL - SM_XH;
    const uint32_t MSTEP = 16 * PADK * 2;   // +16 rows (bytes)

    float acc[2][8][4];
    #pragma unroll
    for (int i = 0; i < 2; i++)
        #pragma unroll
        for (int j = 0; j < 8; j++)
            #pragma unroll
            for (int q = 0; q < 4; q++) acc[i][j][q] = 0.f;

    #pragma unroll 2
    for (int ks = 0; ks < 8; ks++) {
        uint32_t aH[2][4], aL[2][4], bH[4][4], bL[4][4];
        uint32_t ab = aoff + ks * 32;            // +16 cols = 32 bytes
        ldsm4(aH[0], ab);
        ldsm4(aH[1], ab + MSTEP);
        ldsm4(aL[0], ab + DA);
        ldsm4(aL[1], ab + DA + MSTEP);
        uint32_t bb = boff + ks * MSTEP;         // +16 k-rows
        #pragma unroll
        for (int c = 0; c < 4; c++) {
            ldsm4t(bH[c], bb + c * 32);
            ldsm4t(bL[c], bb + c * 32 + DB);
        }
        #pragma unroll
        for (int mt = 0; mt < 2; mt++) {
            #pragma unroll
            for (int nc = 0; nc < 8; nc++) {
                const uint32_t* bh = &bH[nc >> 1][(nc & 1) << 1];
                const uint32_t* bl = &bL[nc >> 1][(nc & 1) << 1];
                mma16816(acc[mt][nc], aH[mt], bh);
                mma16816(acc[mt][nc], aH[mt], bl);
                mma16816(acc[mt][nc], aL[mt], bh);
            }
        }
    }

    // ---- epilogue ----
    const int r = lane >> 2, cq = (lane & 3) << 1;
    #pragma unroll
    for (int mt = 0; mt < 2; mt++) {
        int row0 = m0w + mt * 16 + r;
        int row1 = row0 + 8;
        float S0 = 0.f, B0 = 0.f, S1 = 0.f, B1 = 0.f;
        if (MODE == 0) { S0 = Sp[row0]; B0 = biasp[row0]; S1 = Sp[row1]; B1 = biasp[row1]; }
        float* y0 = Y + (size_t)row0 * HWX + n0;
        float* y1 = Y + (size_t)row1 * HWX + n0;
        #pragma unroll
        for (int nc = 0; nc < 8; nc++) {
            int lc = n0w + nc * 8 + cq;
            float* a4 = acc[mt][nc];
            if (MODE == 0) {
                float rs0 = s_rs[lc], rs1 = s_rs[lc + 1];
                float ms0 = s_ms[lc], ms1 = s_ms[lc + 1];
                *(float2*)(y0 + lc) = make_float2(fmaf(a4[0], rs0, fmaf(-S0, ms0, B0)),
                                                  fmaf(a4[1], rs1, fmaf(-S0, ms1, B0)));
                *(float2*)(y1 + lc) = make_float2(fmaf(a4[2], rs0, fmaf(-S1, ms0, B1)),
                                                  fmaf(a4[3], rs1, fmaf(-S1, ms1, B1)));
            } else {
                *(float2*)(y0 + lc) = make_float2(a4[0], a4[1]);
                *(float2*)(y1 + lc) = make_float2(a4[2], a4[3]);
            }
        }
    }
}

// ---------------------------------------------------------------------------
// K3: depthwise 3x3, smem-tiled, all 6 tensors fused.
// grid (4, 4, 6144), block (32, 8); 32x32 outputs per block, 4 per thread.
// ---------------------------------------------------------------------------
__global__ void __launch_bounds__(256) k_dw(DwArgs da) {
    int zz = blockIdx.z;                // t*1024 + (b*128 + c)
    int t = zz >> 10;
    int pl = zz & 1023;
    int c = pl & 127;
    __shared__ float sm[34][36];
    __shared__ float w9[9];
    __shared__ float bsh;
    int tid = threadIdx.y * 32 + threadIdx.x;
    if (tid < 9) w9[tid] = da.w[t][c * 9 + tid];
    if (tid == 9) bsh = da.b[t][c];

    int h0 = blockIdx.y * 32, w0 = blockIdx.x * 32;
    const float* sp = d_tmp[t] + (size_t)pl * HWX;
    for (int idx = tid; idx < 34 * 34; idx += 256) {
        int rr = idx / 34, cc = idx - rr * 34;
        int gh = h0 - 1 + rr, gw = w0 - 1 + cc;
        float v = 0.f;
        if ((unsigned)gh < 128u && (unsigned)gw < 128u) v = sp[gh * 128 + gw];
        sm[rr][cc] = v;
    }
    __syncthreads();

    float* op = d_qkv[t] + (size_t)pl * HWX;
    int tx = threadIdx.x;
    #pragma unroll
    for (int k = 0; k < 4; k++) {
        int ly = threadIdx.y + 8 * k;
        float a = bsh;
        #pragma unroll
        for (int i = 0; i < 3; i++)
            #pragma unroll
            for (int j = 0; j < 3; j++)
                a = fmaf(w9[i * 3 + j], sm[ly + i][tx + j], a);
        op[(h0 + ly) * 128 + w0 + tx] = a;
    }
}

// ---------------------------------------------------------------------------
// K4: QK logits, split-K (FFMA, memory-streaming).
// ---------------------------------------------------------------------------
__global__ void __launch_bounds__(256) k_qk() {
    const int slab = blockIdx.x;
    const int z = blockIdx.y;
    const int gq = z >> 3, b = z & 7;
    const float* Qb = d_qkv[gq == 0 ? 0 : 3] + (size_t)b * CHW;
    const float* Kb = d_qkv[gq == 0 ? 4 : 1] + (size_t)b * CHW;
    float* P = d_partial[z * 16 + slab];

    __shared__ float Qs[16][128];
    __shared__ float Ks[16][128];
    const int tid = threadIdx.x;
    const int tm = (tid >> 4) << 3;
    const int tn = (tid & 15) << 3;

    float acc[8][8];
    #pragma unroll
    for (int i = 0; i < 8; i++)
        #pragma unroll
        for (int j = 0; j < 8; j++) acc[i][j] = 0.f;

    const int kb = slab << 10;
    for (int k0 = 0; k0 < 1024; k0 += 16) {
        #pragma unroll
        for (int i = 0; i < 2; i++) {
            int id = tid + (i << 8);
            int kk = id >> 5, col = (id & 31) << 2;
            size_t roff = (size_t)(kb + k0 + kk) * 128 + col;
            *(float4*)&Qs[kk][col] = *(const float4*)(Qb + roff);
            *(float4*)&Ks[kk][col] = *(const float4*)(Kb + roff);
        }
        __syncthreads();
        #pragma unroll
        for (int kk = 0; kk < 16; kk++) {
            float av[8], bv[8];
            #pragma unroll
            for (int i = 0; i < 8; i++) av[i] = Qs[kk][tm + i];
            #pragma unroll
            for (int j = 0; j < 8; j++) bv[j] = Ks[kk][tn + j];
            #pragma unroll
            for (int i = 0; i < 8; i++)
                #pragma unroll
                for (int j = 0; j < 8; j++)
                    acc[i][j] = fmaf(av[i], bv[j], acc[i][j]);
        }
        __syncthreads();
    }
    #pragma unroll
    for (int i = 0; i < 8; i++) {
        float* pp = P + (tm + i) * 128 + tn;
        *(float4*)pp       = make_float4(acc[i][0], acc[i][1], acc[i][2], acc[i][3]);
        *(float4*)(pp + 4) = make_float4(acc[i][4], acc[i][5], acc[i][6], acc[i][7]);
    }
}

// ---------------------------------------------------------------------------
// K5: reduce split-K partials + row softmax.
// ---------------------------------------------------------------------------
__global__ void k_softmax() {
    int r = blockIdx.x;
    int gq = r >> 10;
    int rb = r & 1023;
    int b = rb >> 7;
    int cc = rb & 127;
    int d = threadIdx.x;

    const float* pf = &d_partial[0][0];
    size_t base = (size_t)((gq * 8 + b) * 16) * (CHN * CHN) + cc * 128 + d;
    float v = 0.f;
    #pragma unroll
    for (int s = 0; s < 16; s++) v += pf[base + (size_t)s * (CHN * CHN)];

    __shared__ float sm[4];
    __shared__ float ss[4];
    int lane = d & 31, wid = d >> 5;
    float m = v;
    #pragma unroll
    for (int off = 16; off; off >>= 1) m = fmaxf(m, __shfl_xor_sync(0xffffffffu, m, off));
    if (lane == 0) sm[wid] = m;
    __syncthreads();
    m = fmaxf(fmaxf(sm[0], sm[1]), fmaxf(sm[2], sm[3]));

    float e = expf(v - m);
    float sum = e;
    #pragma unroll
    for (int off = 16; off; off >>= 1) sum += __shfl_xor_sync(0xffffffffu, sum, off);
    if (lane == 0) ss[wid] = sum;
    __syncthreads();
    sum = ss[0] + ss[1] + ss[2] + ss[3];

    d_probs[gq][(b * 128 + cc) * 128 + d] = e / sum;
}

// ---------------------------------------------------------------------------
// K7: final linear (FFMA).
// ---------------------------------------------------------------------------
__global__ void __launch_bounds__(256) k_final(const float* lw, const float* lb) {
    const int b = blockIdx.y;
    const int p0 = blockIdx.x << 7;
    const float* A0 = d_att[0] + (size_t)b * CHW;
    const float* A1 = d_att[1] + (size_t)b * CHW;

    __shared__ float Ws[16][129];
    __shared__ float Xs[16][129];
    const int tid = threadIdx.x;
    const int tm = (tid >> 4) << 3;
    const int tn = (tid & 15) << 3;

    float acc[8][8];
    #pragma unroll
    for (int i = 0; i < 8; i++)
        #pragma unroll
        for (int j = 0; j < 8; j++) acc[i][j] = 0.f;

    for (int k0 = 0; k0 < 256; k0 += 16) {
        const float* Xb = (k0 < 128) ? A0 : A1;
        int kq = k0 & 127;
        #pragma unroll
        for (int i = 0; i < 8; i++) {
            int id = tid + (i << 8);
            int co = id >> 4, kk = id & 15;
            Ws[kk][co] = lw[co * 256 + k0 + kk];
        }
        #pragma unroll
        for (int i = 0; i < 8; i++) {
            int id = tid + (i << 8);
            int pp = id >> 4, kk = id & 15;
            Xs[kk][pp] = Xb[(size_t)(p0 + pp) * 128 + kq + kk];
        }
        __syncthreads();
        #pragma unroll
        for (int kk = 0; kk < 16; kk++) {
            float av[8], xv[8];
            #pragma unroll
            for (int i = 0; i < 8; i++) av[i] = Ws[kk][tm + i];
            #pragma unroll
            for (int j = 0; j < 8; j++) xv[j] = Xs[kk][tn + j];
            #pragma unroll
            for (int i = 0; i < 8; i++)
                #pragma unroll
                for (int j = 0; j < 8; j++)
                    acc[i][j] = fmaf(av[i], xv[j], acc[i][j]);
        }
        __syncthreads();
    }

    float* OL = d_outlin + (size_t)b * CHW;
    #pragma unroll
    for (int j = 0; j < 8; j++) {
        float o[8];
        #pragma unroll
        for (int i = 0; i < 8; i++) o[i] = acc[i][j] + lb[tm + i];
        float* yp = OL + (size_t)(p0 + tn + j) * 128 + tm;
        *(float4*)yp       = make_float4(o[0], o[1], o[2], o[3]);
        *(float4*)(yp + 4) = make_float4(o[4], o[5], o[6], o[7]);
    }
}

// ---------------------------------------------------------------------------
// K8: output permutation + residual.
// ---------------------------------------------------------------------------
__global__ void k_perm(const float* Fi, const float* Fw, float* out) {
    int z = blockIdx.z;
    int b = z >> 7;
    int h0 = blockIdx.y * 32;
    int w0 = blockIdx.x * 32;
    int c4 = z & 127;
    __shared__ float s[32][33];
    int tx = threadIdx.x, ty = threadIdx.y;
    const float* OL = d_outlin + (size_t)b * CHW;

    #pragma unroll
    for (int it = 0; it < 4; it++) {
        int wr = ty + it * 8;
        s[wr][tx] = OL[(size_t)((w0 + wr) * 128 + c4) * 128 + h0 + tx];
    }
    __syncthreads();
    #pragma unroll
    for (int it = 0; it < 4; it++) {
        int hl = ty + it * 8;
        size_t idx = (size_t)(z * 128 + (h0 + hl)) * 128 + w0 + tx;
        out[idx] = s[tx][hl] + Fi[idx] + Fw[idx];
    }
}

// ---------------------------------------------------------------------------
// Launch.  Inputs in setup_inputs() dict order (guard on in_sizes[5]).
// ---------------------------------------------------------------------------
extern "C" void kernel_launch(void* const* d_in, const int* in_sizes, int n_in,
                              void* d_out, int out_size) {
    (void)n_in; (void)out_size;
    const float* F_i = (const float*)d_in[0];
    const float* F_w = (const float*)d_in[1];

    const bool interleaved = (in_sizes[5] == 128);

    PtrArgs pa;
    pa.f[0] = F_i;
    pa.f[1] = F_w;
    pa.g[0] = (const float*)d_in[2];
    pa.g[1] = (const float*)d_in[3];

    int w_idx[6], b_idx[6], dw_idx[6], db_idx[6];
    if (interleaved) {
        for (int t = 0; t < 6; t++) {
            w_idx[t]  = 4 + 2 * t;
            b_idx[t]  = 5 + 2 * t;
            dw_idx[t] = 16 + 2 * t;
            db_idx[t] = 17 + 2 * t;
        }
    } else {
        for (int t = 0; t < 6; t++) {
            w_idx[t]  = 4 + t;
            b_idx[t]  = 10 + t;
            dw_idx[t] = 16 + t;
            db_idx[t] = 22 + t;
        }
    }
    DwArgs da;
    for (int t = 0; t < 6; t++) {
        pa.w[t]    = (const float*)d_in[w_idx[t]];
        pa.bias[t] = (const float*)d_in[b_idx[t]];
        da.w[t]    = (const float*)d_in[dw_idx[t]];
        da.b[t]    = (const float*)d_in[db_idx[t]];
    }

    cudaFuncSetAttribute(k_mma<0>, cudaFuncAttributeMaxDynamicSharedMemorySize, SMTOT);
    cudaFuncSetAttribute(k_mma<1>, cudaFuncAttributeMaxDynamicSharedMemorySize, SMTOT);

    // 0) weight*gamma + row sums
    k_prep<<<6 * 128, 128>>>(pa);
    // 1) LN stats
    k_ln<<<dim3(BATCH * HWX / 256, 2), 256>>>(pa);
    // 2) fused LN + 1x1 conv on HMMA tensor cores
    k_mma<0><<<dim3(48, 128), 256, SMTOT>>>(pa);
    // 3) depthwise 3x3 (all 6 fused)
    k_dw<<<dim3(4, 4, 6144), dim3(32, 8)>>>(da);
    // 4) QK logits split-K
    k_qk<<<dim3(16, 16), 256>>>();
    // 5) reduce + softmax
    k_softmax<<<2048, 128>>>();
    // 6) AV GEMMs on HMMA tensor cores
    k_mma<1><<<dim3(16, 128), 256, SMTOT>>>(pa);
    // 7) final linear
    k_final<<<dim3(HWX / 128, BATCH), 256>>>((const float*)d_in[28],
                                             (const float*)d_in[29]);
    // 8) permutation + residual
    k_perm<<<dim3(4, 4, 1024), dim3(32, 8)>>>(F_i, F_w, (float*)d_out);
}

// round 13
// speedup vs baseline: 1.6343x; 1.2879x over previous
#include <cuda_runtime.h>
#include <cuda_bf16.h>
#include <math.h>
#include <stdint.h>

// Problem dims (fixed by the reference)
#define BATCH 8
#define CHN   128
#define HWX   16384                 // 128*128
#define CHW   (CHN*HWX)             // 2097152
#define NPT   (BATCH*CHW)           // 16777216 elements per tensor

// ---------------------------------------------------------------------------
// Scratch (static device globals: allocation-free per harness rules)
// ---------------------------------------------------------------------------
__device__ float d_tmp[6][NPT];        // conv1x1 outputs (pre-depthwise)
__device__ float d_qkv[6][NPT];        // Qi,Ki,Vi,Qw,Kw,Vw after depthwise
__device__ float d_att[2][NPT];        // Aw (0), Ai (1)
__device__ float d_outlin[NPT];        // final linear output
__device__ float d_mean[2][BATCH*HWX];
__device__ float d_rstd[2][BATCH*HWX];
__device__ float d_Wg[6][CHN*CHN];     // conv weights * gamma
__device__ float d_Ssum[6][CHN];       // row sums of Wg
__device__ float d_probs[2][BATCH*CHN*CHN];   // softmax(a1), softmax(a2)
__device__ float d_partial[256][CHN*CHN];     // QK split-K partials

struct PtrArgs {
    const float* f[2];      // F_i, F_w
    const float* g[2];      // g1, g2
    const float* w[6];      // qw1,kw1,vw1,qw2,kw2,vw2
    const float* bias[6];   // conv biases
};
struct DwArgs {
    const float* w[6];
    const float* b[6];
};

// ---------------------------------------------------------------------------
// Helpers (compute_103-safe: ldmatrix + mma.sync only, no tcgen05)
// ---------------------------------------------------------------------------
__device__ __forceinline__ uint32_t s2u(const void* p) {
    uint32_t r;
    asm("{ .reg .u64 t; cvta.to.shared.u64 t, %1; cvt.u32.u64 %0, t; }" : "=r"(r) : "l"(p));
    return r;
}
__device__ __forceinline__ uint32_t pack_bf16(float a, float b) {
    __nv_bfloat162 t = __floats2bfloat162_rn(a, b);
    return *(uint32_t*)&t;
}
__device__ __forceinline__ void ldsm4(uint32_t* r, uint32_t addr) {
    asm volatile("ldmatrix.sync.aligned.m8n8.x4.shared.b16 {%0,%1,%2,%3}, [%4];"
                 : "=r"(r[0]), "=r"(r[1]), "=r"(r[2]), "=r"(r[3]) : "r"(addr));
}
__device__ __forceinline__ void ldsm4t(uint32_t* r, uint32_t addr) {
    asm volatile("ldmatrix.sync.aligned.m8n8.x4.trans.shared.b16 {%0,%1,%2,%3}, [%4];"
                 : "=r"(r[0]), "=r"(r[1]), "=r"(r[2]), "=r"(r[3]) : "r"(addr));
}
// A-operand via trans-ldmatrix from [k][m] smem: fragment order needs {r0,r2,r1,r3}
__device__ __forceinline__ void ldsm4t_A(uint32_t* a, uint32_t addr) {
    uint32_t t[4];
    ldsm4t(t, addr);
    a[0] = t[0]; a[1] = t[2]; a[2] = t[1]; a[3] = t[3];
}
__device__ __forceinline__ void mma16816(float* d, const uint32_t* a, const uint32_t* b) {
    asm volatile(
        "mma.sync.aligned.m16n8k16.row.col.f32.bf16.bf16.f32 "
        "{%0,%1,%2,%3}, {%4,%5,%6,%7}, {%8,%9}, {%0,%1,%2,%3};"
        : "+f"(d[0]), "+f"(d[1]), "+f"(d[2]), "+f"(d[3])
        : "r"(a[0]), "r"(a[1]), "r"(a[2]), "r"(a[3]), "r"(b[0]), "r"(b[1]));
}

// ---------------------------------------------------------------------------
// K0: Wg = W * g, Ssum = row sums of Wg.
// ---------------------------------------------------------------------------
__global__ void k_prep(PtrArgs pa) {
    int t = blockIdx.x >> 7;
    int o = blockIdx.x & 127;
    int c = threadIdx.x;
    const float* gsrc = pa.g[t < 3 ? 0 : 1];
    float v = pa.w[t][o * CHN + c] * gsrc[c];
    d_Wg[t][o * CHN + c] = v;
    float s = v;
    #pragma unroll
    for (int off = 16; off; off >>= 1) s += __shfl_xor_sync(0xffffffffu, s, off);
    __shared__ float sm[4];
    if ((c & 31) == 0) sm[c >> 5] = s;
    __syncthreads();
    if (c == 0) d_Ssum[t][o] = sm[0] + sm[1] + sm[2] + sm[3];
}

// ---------------------------------------------------------------------------
// K1: LayerNorm statistics per pixel.
// ---------------------------------------------------------------------------
__global__ void k_ln(PtrArgs pa) {
    int s = blockIdx.y;
    int p = blockIdx.x * 256 + threadIdx.x;
    int b = p >> 14;
    int hw = p & 16383;
    const float* x = pa.f[s] + (size_t)b * CHW + hw;
    float s1 = 0.f, s2 = 0.f;
    #pragma unroll 16
    for (int c = 0; c < CHN; c++) {
        float v = x[(size_t)c * HWX];
        s1 += v;
        s2 += v * v;
    }
    float m = s1 * (1.0f / CHN);
    float var = s2 * (1.0f / CHN) - m * m;
    d_mean[s][p] = m;
    d_rstd[s][p] = rsqrtf(var + 1e-5f);
}

// ---------------------------------------------------------------------------
// K_MMA: split-bf16 HMMA GEMM, M=128, K=128, N-tile=128 per CTA.
// MODE 0: fused-LN conv1x1 (A = Wg[t], X = raw input [k][n], LN epilogue)
// MODE 1: AV               (A = probs,  X = V buffer [k][n], raw epilogue)
// ---------------------------------------------------------------------------
#define PADK 136
#define SM_AH 1024
#define SM_AL 35840
#define SM_XH 70656
#define SM_XL 105472
#define SMTOT 140288

template <int MODE>
__global__ void __launch_bounds__(256, 1) k_mma(PtrArgs pa) {
    extern __shared__ char dynsm[];
    float* s_rs = (float*)dynsm;
    float* s_ms = (float*)(dynsm + 512);
    __nv_bfloat16* sAH = (__nv_bfloat16*)(dynsm + SM_AH);
    __nv_bfloat16* sAL = (__nv_bfloat16*)(dynsm + SM_AL);
    __nv_bfloat16* sXH = (__nv_bfloat16*)(dynsm + SM_XH);
    __nv_bfloat16* sXL = (__nv_bfloat16*)(dynsm + SM_XL);

    const int tid = threadIdx.x;
    const int z = blockIdx.x;
    const int n0 = blockIdx.y << 7;

    const float* A;
    const float* X;
    float* Y;
    const float *meanp = nullptr, *rstdp = nullptr, *Sp = nullptr, *biasp = nullptr;
    if (MODE == 0) {
        int t = z % 6, b = z / 6;
        int s = (t < 3) ? 0 : 1;
        A = d_Wg[t];
        X = pa.f[s] + (size_t)b * CHW;
        Y = d_tmp[t] + (size_t)b * CHW;
        meanp = d_mean[s] + b * HWX;
        rstdp = d_rstd[s] + b * HWX;
        Sp = d_Ssum[t];
        biasp = pa.bias[t];
    } else {
        int gq = z & 1, b = z >> 1;
        A = d_probs[gq] + b * (CHN * CHN);
        X = d_qkv[gq == 0 ? 5 : 2] + (size_t)b * CHW;
        Y = d_att[gq] + (size_t)b * CHW;
    }

    #pragma unroll
    for (int it = 0; it < 16; it++) {
        int idx = tid + (it << 8);
        int m = idx >> 5, q = (idx & 31) << 2;
        float4 v = *(const float4*)(A + m * CHN + q);
        float h0 = __bfloat162float(__float2bfloat16(v.x));
        float h1 = __bfloat162float(__float2bfloat16(v.y));
        float h2 = __bfloat162float(__float2bfloat16(v.z));
        float h3 = __bfloat162float(__float2bfloat16(v.w));
        *(uint2*)(sAH + m * PADK + q) = make_uint2(pack_bf16(v.x, v.y), pack_bf16(v.z, v.w));
        *(uint2*)(sAL + m * PADK + q) = make_uint2(pack_bf16(v.x - h0, v.y - h1),
                                                   pack_bf16(v.z - h2, v.w - h3));
    }
    #pragma unroll
    for (int it = 0; it < 16; it++) {
        int idx = tid + (it << 8);
        int k = idx >> 5, q = (idx & 31) << 2;
        float4 v = *(const float4*)(X + (size_t)k * HWX + n0 + q);
        float h0 = __bfloat162float(__float2bfloat16(v.x));
        float h1 = __bfloat162float(__float2bfloat16(v.y));
        float h2 = __bfloat162float(__float2bfloat16(v.z));
        float h3 = __bfloat162float(__float2bfloat16(v.w));
        *(uint2*)(sXH + k * PADK + q) = make_uint2(pack_bf16(v.x, v.y), pack_bf16(v.z, v.w));
        *(uint2*)(sXL + k * PADK + q) = make_uint2(pack_bf16(v.x - h0, v.y - h1),
                                                   pack_bf16(v.z - h2, v.w - h3));
    }
    if (MODE == 0 && tid < 128) {
        float rv = rstdp[n0 + tid];
        s_rs[tid] = rv;
        s_ms[tid] = meanp[n0 + tid] * rv;
    }
    __syncthreads();

    const int wid = tid >> 5, lane = tid & 31;
    const int m0w = (wid >> 1) << 5;
    const int n0w = (wid & 1) << 6;
    const int tle = lane >> 3, li = lane & 7;
    const uint32_t smem0 = s2u(dynsm);
    const uint32_t aoff = smem0 + SM_AH +
        (((uint32_t)(m0w + li + ((tle & 1) << 3)) * PADK + ((tle & 2) << 2)) << 1);
    const uint32_t boff = smem0 + SM_XH +
        ((((uint32_t)(li + ((tle & 1) << 3))) * PADK + (uint32_t)n0w + ((tle & 2) << 2)) << 1);
    const uint32_t DA = SM_AL - SM_AH;
    const uint32_t DB = SM_XL - SM_XH;
    const uint32_t MSTEP = 16 * PADK * 2;

    float acc[2][8][4];
    #pragma unroll
    for (int i = 0; i < 2; i++)
        #pragma unroll
        for (int j = 0; j < 8; j++)
            #pragma unroll
            for (int q = 0; q < 4; q++) acc[i][j][q] = 0.f;

    #pragma unroll 2
    for (int ks = 0; ks < 8; ks++) {
        uint32_t aH[2][4], aL[2][4], bH[4][4], bL[4][4];
        uint32_t ab = aoff + ks * 32;
        ldsm4(aH[0], ab);
        ldsm4(aH[1], ab + MSTEP);
        ldsm4(aL[0], ab + DA);
        ldsm4(aL[1], ab + DA + MSTEP);
        uint32_t bb = boff + ks * MSTEP;
        #pragma unroll
        for (int c = 0; c < 4; c++) {
            ldsm4t(bH[c], bb + c * 32);
            ldsm4t(bL[c], bb + c * 32 + DB);
        }
        #pragma unroll
        for (int mt = 0; mt < 2; mt++) {
            #pragma unroll
            for (int nc = 0; nc < 8; nc++) {
                const uint32_t* bh = &bH[nc >> 1][(nc & 1) << 1];
                const uint32_t* bl = &bL[nc >> 1][(nc & 1) << 1];
                mma16816(acc[mt][nc], aH[mt], bh);
                mma16816(acc[mt][nc], aH[mt], bl);
                mma16816(acc[mt][nc], aL[mt], bh);
            }
        }
    }

    const int r = lane >> 2, cq = (lane & 3) << 1;
    #pragma unroll
    for (int mt = 0; mt < 2; mt++) {
        int row0 = m0w + mt * 16 + r;
        int row1 = row0 + 8;
        float S0 = 0.f, B0 = 0.f, S1 = 0.f, B1 = 0.f;
        if (MODE == 0) { S0 = Sp[row0]; B0 = biasp[row0]; S1 = Sp[row1]; B1 = biasp[row1]; }
        float* y0 = Y + (size_t)row0 * HWX + n0;
        float* y1 = Y + (size_t)row1 * HWX + n0;
        #pragma unroll
        for (int nc = 0; nc < 8; nc++) {
            int lc = n0w + nc * 8 + cq;
            float* a4 = acc[mt][nc];
            if (MODE == 0) {
                float rs0 = s_rs[lc], rs1 = s_rs[lc + 1];
                float ms0 = s_ms[lc], ms1 = s_ms[lc + 1];
                *(float2*)(y0 + lc) = make_float2(fmaf(a4[0], rs0, fmaf(-S0, ms0, B0)),
                                                  fmaf(a4[1], rs1, fmaf(-S0, ms1, B0)));
                *(float2*)(y1 + lc) = make_float2(fmaf(a4[2], rs0, fmaf(-S1, ms0, B1)),
                                                  fmaf(a4[3], rs1, fmaf(-S1, ms1, B1)));
            } else {
                *(float2*)(y0 + lc) = make_float2(a4[0], a4[1]);
                *(float2*)(y1 + lc) = make_float2(a4[2], a4[3]);
            }
        }
    }
}

// ---------------------------------------------------------------------------
// K3: depthwise 3x3, register sliding-window, no smem, no inner predicates.
// Block (32,4): covers 128 wide x 32 tall. Thread: 4 wide x 8 tall.
// grid (4 h-tiles, 6144 planes).
// ---------------------------------------------------------------------------
__global__ void __launch_bounds__(128) k_dw2(DwArgs da) {
    int zz = blockIdx.y;               // t*1024 + (b*128+c)
    int t = zz >> 10;
    int pl = zz & 1023;
    int c = pl & 127;
    const float* wd = da.w[t] + c * 9;
    float w00 = wd[0], w01 = wd[1], w02 = wd[2];
    float w10 = wd[3], w11 = wd[4], w12 = wd[5];
    float w20 = wd[6], w21 = wd[7], w22 = wd[8];
    float bias = da.b[t][c];
    const float* sp = d_tmp[t] + (size_t)pl * HWX;
    float* op = d_qkv[t] + (size_t)pl * HWX;

    const int tx = threadIdx.x;
    const int x0 = tx << 2;
    const int h0 = blockIdx.x * 32 + threadIdx.y * 8;

    float4 C[3];
    float L[3], R[3];
    #define LOADROW(hh, s) do { \
        int _h = (hh); \
        if ((unsigned)_h < 128u) { \
            const float* rp = sp + _h * 128; \
            C[s] = *(const float4*)(rp + x0); \
            L[s] = (tx > 0) ? rp[x0 - 1] : 0.f; \
            R[s] = (tx < 31) ? rp[x0 + 4] : 0.f; \
        } else { C[s] = make_float4(0.f, 0.f, 0.f, 0.f); L[s] = 0.f; R[s] = 0.f; } \
    } while (0)

    LOADROW(h0 - 1, 0);
    LOADROW(h0, 1);
    #pragma unroll
    for (int y = 0; y < 8; y++) {
        LOADROW(h0 + y + 1, (y + 2) % 3);
        const int i0 = y % 3, i1 = (y + 1) % 3, i2 = (y + 2) % 3;
        float4 o;
        o.x = bias;
        o.x = fmaf(w00, L[i0],   fmaf(w01, C[i0].x, fmaf(w02, C[i0].y, o.x)));
        o.x = fmaf(w10, L[i1],   fmaf(w11, C[i1].x, fmaf(w12, C[i1].y, o.x)));
        o.x = fmaf(w20, L[i2],   fmaf(w21, C[i2].x, fmaf(w22, C[i2].y, o.x)));
        o.y = bias;
        o.y = fmaf(w00, C[i0].x, fmaf(w01, C[i0].y, fmaf(w02, C[i0].z, o.y)));
        o.y = fmaf(w10, C[i1].x, fmaf(w11, C[i1].y, fmaf(w12, C[i1].z, o.y)));
        o.y = fmaf(w20, C[i2].x, fmaf(w21, C[i2].y, fmaf(w22, C[i2].z, o.y)));
        o.z = bias;
        o.z = fmaf(w00, C[i0].y, fmaf(w01, C[i0].z, fmaf(w02, C[i0].w, o.z)));
        o.z = fmaf(w10, C[i1].y, fmaf(w11, C[i1].z, fmaf(w12, C[i1].w, o.z)));
        o.z = fmaf(w20, C[i2].y, fmaf(w21, C[i2].z, fmaf(w22, C[i2].w, o.z)));
        o.w = bias;
        o.w = fmaf(w00, C[i0].z, fmaf(w01, C[i0].w, fmaf(w02, R[i0], o.w)));
        o.w = fmaf(w10, C[i1].z, fmaf(w11, C[i1].w, fmaf(w12, R[i1], o.w)));
        o.w = fmaf(w20, C[i2].z, fmaf(w21, C[i2].w, fmaf(w22, R[i2], o.w)));
        *(float4*)(op + (h0 + y) * 128 + x0) = o;
    }
    #undef LOADROW
}

// ---------------------------------------------------------------------------
// K4: QK logits, split-K, split-bf16 HMMA. C[c][d] = sum_n Q[n][c] K[n][d].
// A via trans-ldmatrix (permuted frags), B via trans-ldmatrix, both [k][*] smem.
// grid (16 slabs, 16 z), block 256 (8 warps 4x2).
// ---------------------------------------------------------------------------
__global__ void __launch_bounds__(256) k_qk2() {
    __shared__ __nv_bfloat16 sQH[32 * PADK], sQL[32 * PADK];
    __shared__ __nv_bfloat16 sKH[32 * PADK], sKL[32 * PADK];
    const int slab = blockIdx.x;
    const int z = blockIdx.y;
    const int gq = z >> 3, b = z & 7;
    const float* Qb = d_qkv[gq == 0 ? 0 : 3] + (size_t)b * CHW;
    const float* Kb = d_qkv[gq == 0 ? 4 : 1] + (size_t)b * CHW;
    float* P = d_partial[z * 16 + slab];

    const int tid = threadIdx.x, wid = tid >> 5, lane = tid & 31;
    const int m0w = (wid >> 1) << 5;
    const int n0w = (wid & 1) << 6;
    const int tle = lane >> 3, li = lane & 7;
    const uint32_t rowpart = (uint32_t)(li + ((tle & 1) << 3)) * PADK + ((tle & 2) << 2);
    const uint32_t qHa = s2u(sQH) + (rowpart << 1);
    const uint32_t qLa = s2u(sQL) + (rowpart << 1);
    const uint32_t kHa = s2u(sKH) + (rowpart << 1);
    const uint32_t kLa = s2u(sKL) + (rowpart << 1);
    const uint32_t HSTEP = 16 * PADK * 2;      // +16 k-rows in bytes

    float acc[2][8][4];
    #pragma unroll
    for (int i = 0; i < 2; i++)
        #pragma unroll
        for (int j = 0; j < 8; j++)
            #pragma unroll
            for (int q = 0; q < 4; q++) acc[i][j][q] = 0.f;

    const int kb = slab << 10;
    for (int kc = 0; kc < 1024; kc += 32) {
        #pragma unroll
        for (int it = 0; it < 4; it++) {
            int idx = tid + (it << 8);
            int row = idx >> 5, q = (idx & 31) << 2;
            size_t g = (size_t)(kb + kc + row) * 128 + q;
            float4 v = *(const float4*)(Qb + g);
            float h0 = __bfloat162float(__float2bfloat16(v.x));
            float h1 = __bfloat162float(__float2bfloat16(v.y));
            float h2 = __bfloat162float(__float2bfloat16(v.z));
            float h3 = __bfloat162float(__float2bfloat16(v.w));
            *(uint2*)(sQH + row * PADK + q) = make_uint2(pack_bf16(v.x, v.y), pack_bf16(v.z, v.w));
            *(uint2*)(sQL + row * PADK + q) = make_uint2(pack_bf16(v.x - h0, v.y - h1),
                                                         pack_bf16(v.z - h2, v.w - h3));
            float4 u = *(const float4*)(Kb + g);
            float g0 = __bfloat162float(__float2bfloat16(u.x));
            float g1 = __bfloat162float(__float2bfloat16(u.y));
            float g2 = __bfloat162float(__float2bfloat16(u.z));
            float g3 = __bfloat162float(__float2bfloat16(u.w));
            *(uint2*)(sKH + row * PADK + q) = make_uint2(pack_bf16(u.x, u.y), pack_bf16(u.z, u.w));
            *(uint2*)(sKL + row * PADK + q) = make_uint2(pack_bf16(u.x - g0, u.y - g1),
                                                         pack_bf16(u.z - g2, u.w - g3));
        }
        __syncthreads();

        #pragma unroll
        for (int half = 0; half < 2; half++) {
            uint32_t roff = half * HSTEP;
            uint32_t aH[2][4], aL[2][4], bH[4][4], bL[4][4];
            #pragma unroll
            for (int mt = 0; mt < 2; mt++) {
                uint32_t mb = (uint32_t)(m0w + mt * 16) * 2;   // col offset bytes
                ldsm4t_A(aH[mt], qHa + roff + mb);
                ldsm4t_A(aL[mt], qLa + roff + mb);
            }
            #pragma unroll
            for (int c = 0; c < 4; c++) {
                uint32_t nb = (uint32_t)(n0w + c * 16) * 2;
                ldsm4t(bH[c], kHa + roff + nb);
                ldsm4t(bL[c], kLa + roff + nb);
            }
            #pragma unroll
            for (int mt = 0; mt < 2; mt++) {
                #pragma unroll
                for (int nc = 0; nc < 8; nc++) {
                    const uint32_t* bh = &bH[nc >> 1][(nc & 1) << 1];
                    const uint32_t* bl = &bL[nc >> 1][(nc & 1) << 1];
                    mma16816(acc[mt][nc], aH[mt], bh);
                    mma16816(acc[mt][nc], aH[mt], bl);
                    mma16816(acc[mt][nc], aL[mt], bh);
                }
            }
        }
        __syncthreads();
    }

    const int r = lane >> 2, cq = (lane & 3) << 1;
    #pragma unroll
    for (int mt = 0; mt < 2; mt++) {
        int row0 = m0w + mt * 16 + r;
        int row1 = row0 + 8;
        #pragma unroll
        for (int nc = 0; nc < 8; nc++) {
            int lc = n0w + nc * 8 + cq;
            float* a4 = acc[mt][nc];
            *(float2*)(P + row0 * 128 + lc) = make_float2(a4[0], a4[1]);
            *(float2*)(P + row1 * 128 + lc) = make_float2(a4[2], a4[3]);
        }
    }
}

// ---------------------------------------------------------------------------
// K5: reduce split-K partials + row softmax.
// ---------------------------------------------------------------------------
__global__ void k_softmax() {
    int r = blockIdx.x;
    int gq = r >> 10;
    int rb = r & 1023;
    int b = rb >> 7;
    int cc = rb & 127;
    int d = threadIdx.x;

    const float* pf = &d_partial[0][0];
    size_t base = (size_t)((gq * 8 + b) * 16) * (CHN * CHN) + cc * 128 + d;
    float v = 0.f;
    #pragma unroll
    for (int s = 0; s < 16; s++) v += pf[base + (size_t)s * (CHN * CHN)];

    __shared__ float sm[4];
    __shared__ float ss[4];
    int lane = d & 31, wid = d >> 5;
    float m = v;
    #pragma unroll
    for (int off = 16; off; off >>= 1) m = fmaxf(m, __shfl_xor_sync(0xffffffffu, m, off));
    if (lane == 0) sm[wid] = m;
    __syncthreads();
    m = fmaxf(fmaxf(sm[0], sm[1]), fmaxf(sm[2], sm[3]));

    float e = expf(v - m);
    float sum = e;
    #pragma unroll
    for (int off = 16; off; off >>= 1) sum += __shfl_xor_sync(0xffffffffu, sum, off);
    if (lane == 0) ss[wid] = sum;
    __syncthreads();
    sum = ss[0] + ss[1] + ss[2] + ss[3];

    d_probs[gq][(b * 128 + cc) * 128 + d] = e / sum;
}

// ---------------------------------------------------------------------------
// K7: final linear, split-bf16 HMMA. M = p (128-tile), N = co (128), K = 256.
// A = cat rows (contiguous), B = lw transposed into [k][co] smem on fill.
// grid (128, 8), block 256.
// ---------------------------------------------------------------------------
__global__ void __launch_bounds__(256, 1) k_final2(const float* lw, const float* lb) {
    extern __shared__ char dynsm[];
    __nv_bfloat16* sAH = (__nv_bfloat16*)(dynsm + SM_AH);
    __nv_bfloat16* sAL = (__nv_bfloat16*)(dynsm + SM_AL);
    __nv_bfloat16* sXH = (__nv_bfloat16*)(dynsm + SM_XH);
    __nv_bfloat16* sXL = (__nv_bfloat16*)(dynsm + SM_XL);

    const int tid = threadIdx.x;
    const int b = blockIdx.y;
    const int p0 = blockIdx.x << 7;

    const int wid = tid >> 5, lane = tid & 31;
    const int m0w = (wid >> 1) << 5;
    const int n0w = (wid & 1) << 6;
    const int tle = lane >> 3, li = lane & 7;
    const uint32_t smem0 = s2u(dynsm);
    const uint32_t aoff = smem0 + SM_AH +
        (((uint32_t)(m0w + li + ((tle & 1) << 3)) * PADK + ((tle & 2) << 2)) << 1);
    const uint32_t boff = smem0 + SM_XH +
        ((((uint32_t)(li + ((tle & 1) << 3))) * PADK + (uint32_t)n0w + ((tle & 2) << 2)) << 1);
    const uint32_t DA = SM_AL - SM_AH;
    const uint32_t DB = SM_XL - SM_XH;
    const uint32_t MSTEP = 16 * PADK * 2;

    float acc[2][8][4];
    #pragma unroll
    for (int i = 0; i < 2; i++)
        #pragma unroll
        for (int j = 0; j < 8; j++)
            #pragma unroll
            for (int q = 0; q < 4; q++) acc[i][j][q] = 0.f;

    #pragma unroll
    for (int half = 0; half < 2; half++) {
        const float* Ab = d_att[half] + (size_t)b * CHW + (size_t)p0 * 128;
        #pragma unroll
        for (int it = 0; it < 16; it++) {
            int idx = tid + (it << 8);
            int m = idx >> 5, q = (idx & 31) << 2;
            float4 v = *(const float4*)(Ab + m * 128 + q);
            float h0 = __bfloat162float(__float2bfloat16(v.x));
            float h1 = __bfloat162float(__float2bfloat16(v.y));
            float h2 = __bfloat162float(__float2bfloat16(v.z));
            float h3 = __bfloat162float(__float2bfloat16(v.w));
            *(uint2*)(sAH + m * PADK + q) = make_uint2(pack_bf16(v.x, v.y), pack_bf16(v.z, v.w));
            *(uint2*)(sAL + m * PADK + q) = make_uint2(pack_bf16(v.x - h0, v.y - h1),
                                                       pack_bf16(v.z - h2, v.w - h3));
        }
        // B fill: lw[co][half*128 + k] transposed -> sX[k][co]
        #pragma unroll
        for (int it = 0; it < 16; it++) {
            int idx = tid + (it << 8);
            int co = idx >> 5, q = (idx & 31) << 2;
            float4 v = *(const float4*)(lw + co * 256 + half * 128 + q);
            float h0 = __bfloat162float(__float2bfloat16(v.x));
            float h1 = __bfloat162float(__float2bfloat16(v.y));
            float h2 = __bfloat162float(__float2bfloat16(v.z));
            float h3 = __bfloat162float(__float2bfloat16(v.w));
            sXH[(q + 0) * PADK + co] = __float2bfloat16(v.x);
            sXH[(q + 1) * PADK + co] = __float2bfloat16(v.y);
            sXH[(q + 2) * PADK + co] = __float2bfloat16(v.z);
            sXH[(q + 3) * PADK + co] = __float2bfloat16(v.w);
            sXL[(q + 0) * PADK + co] = __float2bfloat16(v.x - h0);
            sXL[(q + 1) * PADK + co] = __float2bfloat16(v.y - h1);
            sXL[(q + 2) * PADK + co] = __float2bfloat16(v.z - h2);
            sXL[(q + 3) * PADK + co] = __float2bfloat16(v.w - h3);
        }
        __syncthreads();

        #pragma unroll 2
        for (int ks = 0; ks < 8; ks++) {
            uint32_t aH[2][4], aL[2][4], bH[4][4], bL[4][4];
            uint32_t ab = aoff + ks * 32;
            ldsm4(aH[0], ab);
            ldsm4(aH[1], ab + MSTEP);
            ldsm4(aL[0], ab + DA);
            ldsm4(aL[1], ab + DA + MSTEP);
            uint32_t bb = boff + ks * MSTEP;
            #pragma unroll
            for (int c = 0; c < 4; c++) {
                ldsm4t(bH[c], bb + c * 32);
                ldsm4t(bL[c], bb + c * 32 + DB);
            }
            #pragma unroll
            for (int mt = 0; mt < 2; mt++) {
                #pragma unroll
                for (int nc = 0; nc < 8; nc++) {
                    const uint32_t* bh = &bH[nc >> 1][(nc & 1) << 1];
                    const uint32_t* bl = &bL[nc >> 1][(nc & 1) << 1];
                    mma16816(acc[mt][nc], aH[mt], bh);
                    mma16816(acc[mt][nc], aH[mt], bl);
                    mma16816(acc[mt][nc], aL[mt], bh);
                }
            }
        }
        __syncthreads();
    }

    float* OL = d_outlin + (size_t)b * CHW;
    const int r = lane >> 2, cq = (lane & 3) << 1;
    #pragma unroll
    for (int mt = 0; mt < 2; mt++) {
        int row0 = p0 + m0w + mt * 16 + r;
        int row1 = row0 + 8;
        #pragma unroll
        for (int nc = 0; nc < 8; nc++) {
            int lc = n0w + nc * 8 + cq;
            float* a4 = acc[mt][nc];
            float b0 = lb[lc], b1 = lb[lc + 1];
            *(float2*)(OL + (size_t)row0 * 128 + lc) = make_float2(a4[0] + b0, a4[1] + b1);
            *(float2*)(OL + (size_t)row1 * 128 + lc) = make_float2(a4[2] + b0, a4[3] + b1);
        }
    }
}

// ---------------------------------------------------------------------------
// K8: output permutation + residual.
// ---------------------------------------------------------------------------
__global__ void k_perm(const float* Fi, const float* Fw, float* out) {
    int z = blockIdx.z;
    int b = z >> 7;
    int h0 = blockIdx.y * 32;
    int w0 = blockIdx.x * 32;
    int c4 = z & 127;
    __shared__ float s[32][33];
    int tx = threadIdx.x, ty = threadIdx.y;
    const float* OL = d_outlin + (size_t)b * CHW;

    #pragma unroll
    for (int it = 0; it < 4; it++) {
        int wr = ty + it * 8;
        s[wr][tx] = OL[(size_t)((w0 + wr) * 128 + c4) * 128 + h0 + tx];
    }
    __syncthreads();
    #pragma unroll
    for (int it = 0; it < 4; it++) {
        int hl = ty + it * 8;
        size_t idx = (size_t)(z * 128 + (h0 + hl)) * 128 + w0 + tx;
        out[idx] = s[tx][hl] + Fi[idx] + Fw[idx];
    }
}

// ---------------------------------------------------------------------------
// Launch.  Inputs in setup_inputs() dict order (guard on in_sizes[5]).
// ---------------------------------------------------------------------------
extern "C" void kernel_launch(void* const* d_in, const int* in_sizes, int n_in,
                              void* d_out, int out_size) {
    (void)n_in; (void)out_size;
    const float* F_i = (const float*)d_in[0];
    const float* F_w = (const float*)d_in[1];

    const bool interleaved = (in_sizes[5] == 128);

    PtrArgs pa;
    pa.f[0] = F_i;
    pa.f[1] = F_w;
    pa.g[0] = (const float*)d_in[2];
    pa.g[1] = (const float*)d_in[3];

    int w_idx[6], b_idx[6], dw_idx[6], db_idx[6];
    if (interleaved) {
        for (int t = 0; t < 6; t++) {
            w_idx[t]  = 4 + 2 * t;
            b_idx[t]  = 5 + 2 * t;
            dw_idx[t] = 16 + 2 * t;
            db_idx[t] = 17 + 2 * t;
        }
    } else {
        for (int t = 0; t < 6; t++) {
            w_idx[t]  = 4 + t;
            b_idx[t]  = 10 + t;
            dw_idx[t] = 16 + t;
            db_idx[t] = 22 + t;
        }
    }
    DwArgs da;
    for (int t = 0; t < 6; t++) {
        pa.w[t]    = (const float*)d_in[w_idx[t]];
        pa.bias[t] = (const float*)d_in[b_idx[t]];
        da.w[t]    = (const float*)d_in[dw_idx[t]];
        da.b[t]    = (const float*)d_in[db_idx[t]];
    }

    cudaFuncSetAttribute(k_mma<0>, cudaFuncAttributeMaxDynamicSharedMemorySize, SMTOT);
    cudaFuncSetAttribute(k_mma<1>, cudaFuncAttributeMaxDynamicSharedMemorySize, SMTOT);
    cudaFuncSetAttribute(k_final2, cudaFuncAttributeMaxDynamicSharedMemorySize, SMTOT);

    // 0) weight*gamma + row sums
    k_prep<<<6 * 128, 128>>>(pa);
    // 1) LN stats
    k_ln<<<dim3(BATCH * HWX / 256, 2), 256>>>(pa);
    // 2) fused LN + 1x1 conv on HMMA tensor cores
    k_mma<0><<<dim3(48, 128), 256, SMTOT>>>(pa);
    // 3) depthwise 3x3 (register sliding window)
    k_dw2<<<dim3(4, 6144), dim3(32, 4)>>>(da);
    // 4) QK logits split-K on HMMA
    k_qk2<<<dim3(16, 16), 256>>>();
    // 5) reduce + softmax
    k_softmax<<<2048, 128>>>();
    // 6) AV GEMMs on HMMA tensor cores
    k_mma<1><<<dim3(16, 128), 256, SMTOT>>>(pa);
    // 7) final linear on HMMA
    k_final2<<<dim3(128, 8), 256, SMTOT>>>((const float*)d_in[28],
                                           (const float*)d_in[29]);
    // 8) permutation + residual
    k_perm<<<dim3(4, 4, 1024), dim3(32, 8)>>>(F_i, F_w, (float*)d_out);
}

// round 16
// speedup vs baseline: 1.8284x; 1.1188x over previous
#include <cuda_runtime.h>
#include <cuda_bf16.h>
#include <math.h>
#include <stdint.h>

// Problem dims (fixed by the reference)
#define BATCH 8
#define CHN   128
#define HWX   16384                 // 128*128
#define CHW   (CHN*HWX)             // 2097152
#define NPT   (BATCH*CHW)           // 16777216 elements per tensor

// ---------------------------------------------------------------------------
// Scratch (static device globals: allocation-free per harness rules)
// ---------------------------------------------------------------------------
__device__ float d_tmp[6][NPT];        // conv1x1 outputs (pre-depthwise)
__device__ float d_qkv[6][NPT];        // Qi,Ki,Vi,Qw,Kw,Vw after depthwise
__device__ float d_att[2][NPT];        // Aw (0), Ai (1)
__device__ float d_mean[2][BATCH*HWX];
__device__ float d_rstd[2][BATCH*HWX];
__device__ float d_Wg[6][CHN*CHN];     // conv weights * gamma
__device__ float d_Ssum[6][CHN];       // row sums of Wg
__device__ float d_probs[2][BATCH*CHN*CHN];   // softmax(a1), softmax(a2)
__device__ float d_partial[256][CHN*CHN];     // QK split-K partials

struct PtrArgs {
    const float* f[2];      // F_i, F_w
    const float* g[2];      // g1, g2
    const float* w[6];      // qw1,kw1,vw1,qw2,kw2,vw2
    const float* bias[6];   // conv biases
};
struct DwArgs {
    const float* w[6];
    const float* b[6];
};

// ---------------------------------------------------------------------------
// Helpers (compute_103-safe: ldmatrix + mma.sync only, no tcgen05)
// ---------------------------------------------------------------------------
__device__ __forceinline__ uint32_t s2u(const void* p) {
    uint32_t r;
    asm("{ .reg .u64 t; cvta.to.shared.u64 t, %1; cvt.u32.u64 %0, t; }" : "=r"(r) : "l"(p));
    return r;
}
__device__ __forceinline__ uint32_t pack_bf16(float a, float b) {
    __nv_bfloat162 t = __floats2bfloat162_rn(a, b);
    return *(uint32_t*)&t;
}
__device__ __forceinline__ void ldsm4(uint32_t* r, uint32_t addr) {
    asm volatile("ldmatrix.sync.aligned.m8n8.x4.shared.b16 {%0,%1,%2,%3}, [%4];"
                 : "=r"(r[0]), "=r"(r[1]), "=r"(r[2]), "=r"(r[3]) : "r"(addr));
}
__device__ __forceinline__ void ldsm4t(uint32_t* r, uint32_t addr) {
    asm volatile("ldmatrix.sync.aligned.m8n8.x4.trans.shared.b16 {%0,%1,%2,%3}, [%4];"
                 : "=r"(r[0]), "=r"(r[1]), "=r"(r[2]), "=r"(r[3]) : "r"(addr));
}
// A-operand via trans-ldmatrix from [k][m] smem: fragment order needs {r0,r2,r1,r3}
__device__ __forceinline__ void ldsm4t_A(uint32_t* a, uint32_t addr) {
    uint32_t t[4];
    ldsm4t(t, addr);
    a[0] = t[0]; a[1] = t[2]; a[2] = t[1]; a[3] = t[3];
}
__device__ __forceinline__ void mma16816(float* d, const uint32_t* a, const uint32_t* b) {
    asm volatile(
        "mma.sync.aligned.m16n8k16.row.col.f32.bf16.bf16.f32 "
        "{%0,%1,%2,%3}, {%4,%5,%6,%7}, {%8,%9}, {%0,%1,%2,%3};"
        : "+f"(d[0]), "+f"(d[1]), "+f"(d[2]), "+f"(d[3])
        : "r"(a[0]), "r"(a[1]), "r"(a[2]), "r"(a[3]), "r"(b[0]), "r"(b[1]));
}
// split a float4 into hi/lo bf16 pairs
__device__ __forceinline__ void split4(float4 v, uint2& hi, uint2& lo) {
    float h0 = __bfloat162float(__float2bfloat16(v.x));
    float h1 = __bfloat162float(__float2bfloat16(v.y));
    float h2 = __bfloat162float(__float2bfloat16(v.z));
    float h3 = __bfloat162float(__float2bfloat16(v.w));
    hi = make_uint2(pack_bf16(v.x, v.y), pack_bf16(v.z, v.w));
    lo = make_uint2(pack_bf16(v.x - h0, v.y - h1), pack_bf16(v.z - h2, v.w - h3));
}

#define PADK 136

// ---------------------------------------------------------------------------
// K0: Wg = W * g, Ssum = row sums of Wg.
// ---------------------------------------------------------------------------
__global__ void k_prep(PtrArgs pa) {
    int t = blockIdx.x >> 7;
    int o = blockIdx.x & 127;
    int c = threadIdx.x;
    const float* gsrc = pa.g[t < 3 ? 0 : 1];
    float v = pa.w[t][o * CHN + c] * gsrc[c];
    d_Wg[t][o * CHN + c] = v;
    float s = v;
    #pragma unroll
    for (int off = 16; off; off >>= 1) s += __shfl_xor_sync(0xffffffffu, s, off);
    __shared__ float sm[4];
    if ((c & 31) == 0) sm[c >> 5] = s;
    __syncthreads();
    if (c == 0) d_Ssum[t][o] = sm[0] + sm[1] + sm[2] + sm[3];
}

// ---------------------------------------------------------------------------
// K1: LayerNorm statistics per pixel.
// ---------------------------------------------------------------------------
__global__ void k_ln(PtrArgs pa) {
    int s = blockIdx.y;
    int p = blockIdx.x * 256 + threadIdx.x;
    int b = p >> 14;
    int hw = p & 16383;
    const float* x = pa.f[s] + (size_t)b * CHW + hw;
    float s1 = 0.f, s2 = 0.f;
    #pragma unroll 16
    for (int c = 0; c < CHN; c++) {
        float v = x[(size_t)c * HWX];
        s1 += v;
        s2 += v * v;
    }
    float m = s1 * (1.0f / CHN);
    float var = s2 * (1.0f / CHN) - m * m;
    d_mean[s][p] = m;
    d_rstd[s][p] = rsqrtf(var + 1e-5f);
}

// ---------------------------------------------------------------------------
// K_MMA v2: split-bf16 HMMA GEMM, persistent A + pipelined X chunks.
// M=128, K=128; each CTA processes NT=4 n-tiles of 128.
// X streamed in K=64 chunks through ping-pong smem buffers; LDG of next
// chunk issued before MMA of current chunk (latency hidden).
// SMEM: AH 0..34816, AL ..69632, Xbuf(h) at 69632 + h*34816 (XH then XL 17408).
// ---------------------------------------------------------------------------
#define NT 4
#define SMTOT2 139264

template <int MODE>
__global__ void __launch_bounds__(256, 1) k_mma(PtrArgs pa) {
    extern __shared__ char dynsm[];
    __nv_bfloat16* sAH = (__nv_bfloat16*)(dynsm);
    __nv_bfloat16* sAL = (__nv_bfloat16*)(dynsm + 34816);

    const int tid = threadIdx.x;
    const int z = blockIdx.x;

    const float* A;
    const float* X;
    float* Y;
    const float *meanp = nullptr, *rstdp = nullptr, *Sp = nullptr, *biasp = nullptr;
    if (MODE == 0) {
        int t = z % 6, b = z / 6;
        int s = (t < 3) ? 0 : 1;
        A = d_Wg[t];
        X = pa.f[s] + (size_t)b * CHW;
        Y = d_tmp[t] + (size_t)b * CHW;
        meanp = d_mean[s] + b * HWX;
        rstdp = d_rstd[s] + b * HWX;
        Sp = d_Ssum[t];
        biasp = pa.bias[t];
    } else {
        int gq = z & 1, b = z >> 1;
        A = d_probs[gq] + b * (CHN * CHN);
        X = d_qkv[gq == 0 ? 5 : 2] + (size_t)b * CHW;
        Y = d_att[gq] + (size_t)b * CHW;
    }

    // ---- A fill (once per CTA) ----
    #pragma unroll
    for (int it = 0; it < 16; it++) {
        int idx = tid + (it << 8);
        int m = idx >> 5, q = (idx & 31) << 2;
        float4 v = *(const float4*)(A + m * CHN + q);
        uint2 hi, lo;
        split4(v, hi, lo);
        *(uint2*)(sAH + m * PADK + q) = hi;
        *(uint2*)(sAL + m * PADK + q) = lo;
    }

    const int wid = tid >> 5, lane = tid & 31;
    const int m0w = (wid >> 1) << 5;
    const int n0w = (wid & 1) << 6;
    const int tle = lane >> 3, li = lane & 7;
    const uint32_t smem0 = s2u(dynsm);
    const uint32_t aoff = smem0 +
        (((uint32_t)(m0w + li + ((tle & 1) << 3)) * PADK + ((tle & 2) << 2)) << 1);
    const uint32_t brow =
        (((uint32_t)(li + ((tle & 1) << 3)) * PADK + (uint32_t)n0w + ((tle & 2) << 2)) << 1);
    const uint32_t DA = 34816u;       // AH -> AL
    const uint32_t DXB = 17408u;      // XH -> XL within a buffer
    const uint32_t MSTEP = 16 * PADK * 2;

    const int rowf = tid >> 5;        // fill row base (0..7)
    const int qf = (tid & 31) << 2;

    float acc[2][8][4];
    #pragma unroll
    for (int i = 0; i < 2; i++)
        #pragma unroll
        for (int j = 0; j < 8; j++)
            #pragma unroll
            for (int q = 0; q < 4; q++) acc[i][j][q] = 0.f;

    float4 R[8];
    // prologue: LDG chunk (j=0, h=0)
    {
        int n00 = (blockIdx.y * NT) << 7;
        const float* Xb = X + (size_t)rowf * HWX + n00 + qf;
        #pragma unroll
        for (int it = 0; it < 8; it++)
            R[it] = *(const float4*)(Xb + (size_t)(it * 8) * HWX);
    }

    for (int j = 0; j < NT; j++) {
        const int n0 = ((blockIdx.y * NT + j) << 7);
        #pragma unroll
        for (int h = 0; h < 2; h++) {
            // STS current chunk into buf h
            {
                __nv_bfloat16* XH = (__nv_bfloat16*)(dynsm + 69632 + h * 34816);
                __nv_bfloat16* XL = XH + 8704;
                #pragma unroll
                for (int it = 0; it < 8; it++) {
                    int row = rowf + it * 8;
                    uint2 hi, lo;
                    split4(R[it], hi, lo);
                    *(uint2*)(XH + row * PADK + qf) = hi;
                    *(uint2*)(XL + row * PADK + qf) = lo;
                }
            }
            // prefetch next chunk (overlaps with this chunk's MMA)
            if (!((j == NT - 1) && (h == 1))) {
                int jn = (h == 0) ? j : j + 1;
                int hn = (h == 0) ? 1 : 0;
                int n0n = ((blockIdx.y * NT + jn) << 7);
                const float* Xb = X + (size_t)(hn * 64 + rowf) * HWX + n0n + qf;
                #pragma unroll
                for (int it = 0; it < 8; it++)
                    R[it] = *(const float4*)(Xb + (size_t)(it * 8) * HWX);
            }
            __syncthreads();
            // MMA on buf h (A columns h*64..h*64+63)
            uint32_t abase = aoff + h * 128;
            uint32_t bbase = smem0 + 69632 + h * 34816 + brow;
            #pragma unroll
            for (int ks = 0; ks < 4; ks++) {
                uint32_t aH[2][4], aL[2][4], bH[4][4], bL[4][4];
                uint32_t ab = abase + ks * 32;
                ldsm4(aH[0], ab);
                ldsm4(aH[1], ab + MSTEP);
                ldsm4(aL[0], ab + DA);
                ldsm4(aL[1], ab + DA + MSTEP);
                uint32_t bb = bbase + ks * MSTEP;
                #pragma unroll
                for (int c = 0; c < 4; c++) {
                    ldsm4t(bH[c], bb + c * 32);
                    ldsm4t(bL[c], bb + c * 32 + DXB);
                }
                #pragma unroll
                for (int mt = 0; mt < 2; mt++) {
                    #pragma unroll
                    for (int nc = 0; nc < 8; nc++) {
                        const uint32_t* bh = &bH[nc >> 1][(nc & 1) << 1];
                        const uint32_t* bl = &bL[nc >> 1][(nc & 1) << 1];
                        mma16816(acc[mt][nc], aH[mt], bh);
                        mma16816(acc[mt][nc], aH[mt], bl);
                        mma16816(acc[mt][nc], aL[mt], bh);
                    }
                }
            }
        }

        // ---- epilogue tile j ----
        const int r = lane >> 2, cq = (lane & 3) << 1;
        #pragma unroll
        for (int mt = 0; mt < 2; mt++) {
            int row0 = m0w + mt * 16 + r;
            int row1 = row0 + 8;
            float S0 = 0.f, B0 = 0.f, S1 = 0.f, B1 = 0.f;
            if (MODE == 0) { S0 = Sp[row0]; B0 = biasp[row0]; S1 = Sp[row1]; B1 = biasp[row1]; }
            float* y0 = Y + (size_t)row0 * HWX + n0;
            float* y1 = Y + (size_t)row1 * HWX + n0;
            #pragma unroll
            for (int nc = 0; nc < 8; nc++) {
                int lc = n0w + nc * 8 + cq;
                float* a4 = acc[mt][nc];
                if (MODE == 0) {
                    float rs0 = rstdp[n0 + lc], rs1 = rstdp[n0 + lc + 1];
                    float ms0 = meanp[n0 + lc] * rs0, ms1 = meanp[n0 + lc + 1] * rs1;
                    *(float2*)(y0 + lc) = make_float2(fmaf(a4[0], rs0, fmaf(-S0, ms0, B0)),
                                                      fmaf(a4[1], rs1, fmaf(-S0, ms1, B0)));
                    *(float2*)(y1 + lc) = make_float2(fmaf(a4[2], rs0, fmaf(-S1, ms0, B1)),
                                                      fmaf(a4[3], rs1, fmaf(-S1, ms1, B1)));
                } else {
                    *(float2*)(y0 + lc) = make_float2(a4[0], a4[1]);
                    *(float2*)(y1 + lc) = make_float2(a4[2], a4[3]);
                }
                a4[0] = a4[1] = a4[2] = a4[3] = 0.f;
            }
        }
    }
}

// ---------------------------------------------------------------------------
// K3: depthwise 3x3, register sliding-window (DRAM-bound, 80% of spec).
// ---------------------------------------------------------------------------
__global__ void __launch_bounds__(128) k_dw2(DwArgs da) {
    int zz = blockIdx.y;               // t*1024 + (b*128+c)
    int t = zz >> 10;
    int pl = zz & 1023;
    int c = pl & 127;
    const float* wd = da.w[t] + c * 9;
    float w00 = wd[0], w01 = wd[1], w02 = wd[2];
    float w10 = wd[3], w11 = wd[4], w12 = wd[5];
    float w20 = wd[6], w21 = wd[7], w22 = wd[8];
    float bias = da.b[t][c];
    const float* sp = d_tmp[t] + (size_t)pl * HWX;
    float* op = d_qkv[t] + (size_t)pl * HWX;

    const int tx = threadIdx.x;
    const int x0 = tx << 2;
    const int h0 = blockIdx.x * 32 + threadIdx.y * 8;

    float4 C[3];
    float L[3], R[3];
    #define LOADROW(hh, s) do { \
        int _h = (hh); \
        if ((unsigned)_h < 128u) { \
            const float* rp = sp + _h * 128; \
            C[s] = *(const float4*)(rp + x0); \
            L[s] = (tx > 0) ? rp[x0 - 1] : 0.f; \
            R[s] = (tx < 31) ? rp[x0 + 4] : 0.f; \
        } else { C[s] = make_float4(0.f, 0.f, 0.f, 0.f); L[s] = 0.f; R[s] = 0.f; } \
    } while (0)

    LOADROW(h0 - 1, 0);
    LOADROW(h0, 1);
    #pragma unroll
    for (int y = 0; y < 8; y++) {
        LOADROW(h0 + y + 1, (y + 2) % 3);
        const int i0 = y % 3, i1 = (y + 1) % 3, i2 = (y + 2) % 3;
        float4 o;
        o.x = bias;
        o.x = fmaf(w00, L[i0],   fmaf(w01, C[i0].x, fmaf(w02, C[i0].y, o.x)));
        o.x = fmaf(w10, L[i1],   fmaf(w11, C[i1].x, fmaf(w12, C[i1].y, o.x)));
        o.x = fmaf(w20, L[i2],   fmaf(w21, C[i2].x, fmaf(w22, C[i2].y, o.x)));
        o.y = bias;
        o.y = fmaf(w00, C[i0].x, fmaf(w01, C[i0].y, fmaf(w02, C[i0].z, o.y)));
        o.y = fmaf(w10, C[i1].x, fmaf(w11, C[i1].y, fmaf(w12, C[i1].z, o.y)));
        o.y = fmaf(w20, C[i2].x, fmaf(w21, C[i2].y, fmaf(w22, C[i2].z, o.y)));
        o.z = bias;
        o.z = fmaf(w00, C[i0].y, fmaf(w01, C[i0].z, fmaf(w02, C[i0].w, o.z)));
        o.z = fmaf(w10, C[i1].y, fmaf(w11, C[i1].z, fmaf(w12, C[i1].w, o.z)));
        o.z = fmaf(w20, C[i2].y, fmaf(w21, C[i2].z, fmaf(w22, C[i2].w, o.z)));
        o.w = bias;
        o.w = fmaf(w00, C[i0].z, fmaf(w01, C[i0].w, fmaf(w02, R[i0], o.w)));
        o.w = fmaf(w10, C[i1].z, fmaf(w11, C[i1].w, fmaf(w12, R[i1], o.w)));
        o.w = fmaf(w20, C[i2].z, fmaf(w21, C[i2].w, fmaf(w22, R[i2], o.w)));
        *(float4*)(op + (h0 + y) * 128 + x0) = o;
    }
    #undef LOADROW
}

// ---------------------------------------------------------------------------
// K4: QK logits, split-K, split-bf16 HMMA with LDG-ahead prefetch.
// grid (16 slabs, 16 z), block 256 (8 warps 4x2).
// ---------------------------------------------------------------------------
__global__ void __launch_bounds__(256) k_qk2() {
    __shared__ __nv_bfloat16 sQH[32 * PADK], sQL[32 * PADK];
    __shared__ __nv_bfloat16 sKH[32 * PADK], sKL[32 * PADK];
    const int slab = blockIdx.x;
    const int z = blockIdx.y;
    const int gq = z >> 3, b = z & 7;
    const float* Qb = d_qkv[gq == 0 ? 0 : 3] + (size_t)b * CHW;
    const float* Kb = d_qkv[gq == 0 ? 4 : 1] + (size_t)b * CHW;
    float* P = d_partial[z * 16 + slab];

    const int tid = threadIdx.x, wid = tid >> 5, lane = tid & 31;
    const int m0w = (wid >> 1) << 5;
    const int n0w = (wid & 1) << 6;
    const int tle = lane >> 3, li = lane & 7;
    const uint32_t rowpart = (uint32_t)(li + ((tle & 1) << 3)) * PADK + ((tle & 2) << 2);
    const uint32_t qHa = s2u(sQH) + (rowpart << 1);
    const uint32_t qLa = s2u(sQL) + (rowpart << 1);
    const uint32_t kHa = s2u(sKH) + (rowpart << 1);
    const uint32_t kLa = s2u(sKL) + (rowpart << 1);
    const uint32_t HSTEP = 16 * PADK * 2;

    const int rowf = tid >> 5;
    const int qf = (tid & 31) << 2;

    float acc[2][8][4];
    #pragma unroll
    for (int i = 0; i < 2; i++)
        #pragma unroll
        for (int j = 0; j < 8; j++)
            #pragma unroll
            for (int q = 0; q < 4; q++) acc[i][j][q] = 0.f;

    const int kb = slab << 10;

    float4 Rq[4], Rk[4];
    // prologue: chunk 0
    #pragma unroll
    for (int it = 0; it < 4; it++) {
        size_t g = (size_t)(kb + rowf + it * 8) * 128 + qf;
        Rq[it] = *(const float4*)(Qb + g);
        Rk[it] = *(const float4*)(Kb + g);
    }

    for (int kc = 0; kc < 1024; kc += 32) {
        // convert + STS current chunk
        #pragma unroll
        for (int it = 0; it < 4; it++) {
            int row = rowf + it * 8;
            uint2 hi, lo;
            split4(Rq[it], hi, lo);
            *(uint2*)(sQH + row * PADK + qf) = hi;
            *(uint2*)(sQL + row * PADK + qf) = lo;
            split4(Rk[it], hi, lo);
            *(uint2*)(sKH + row * PADK + qf) = hi;
            *(uint2*)(sKL + row * PADK + qf) = lo;
        }
        // prefetch next chunk (hidden behind MMA)
        if (kc + 32 < 1024) {
            #pragma unroll
            for (int it = 0; it < 4; it++) {
                size_t g = (size_t)(kb + kc + 32 + rowf + it * 8) * 128 + qf;
                Rq[it] = *(const float4*)(Qb + g);
                Rk[it] = *(const float4*)(Kb + g);
            }
        }
        __syncthreads();

        #pragma unroll
        for (int half = 0; half < 2; half++) {
            uint32_t roff = half * HSTEP;
            uint32_t aH[2][4], aL[2][4], bH[4][4], bL[4][4];
            #pragma unroll
            for (int mt = 0; mt < 2; mt++) {
                uint32_t mb = (uint32_t)(m0w + mt * 16) * 2;
                ldsm4t_A(aH[mt], qHa + roff + mb);
                ldsm4t_A(aL[mt], qLa + roff + mb);
            }
            #pragma unroll
            for (int c = 0; c < 4; c++) {
                uint32_t nb = (uint32_t)(n0w + c * 16) * 2;
                ldsm4t(bH[c], kHa + roff + nb);
                ldsm4t(bL[c], kLa + roff + nb);
            }
            #pragma unroll
            for (int mt = 0; mt < 2; mt++) {
                #pragma unroll
                for (int nc = 0; nc < 8; nc++) {
                    const uint32_t* bh = &bH[nc >> 1][(nc & 1) << 1];
                    const uint32_t* bl = &bL[nc >> 1][(nc & 1) << 1];
                    mma16816(acc[mt][nc], aH[mt], bh);
                    mma16816(acc[mt][nc], aH[mt], bl);
                    mma16816(acc[mt][nc], aL[mt], bh);
                }
            }
        }
        __syncthreads();
    }

    const int r = lane >> 2, cq = (lane & 3) << 1;
    #pragma unroll
    for (int mt = 0; mt < 2; mt++) {
        int row0 = m0w + mt * 16 + r;
        int row1 = row0 + 8;
        #pragma unroll
        for (int nc = 0; nc < 8; nc++) {
            int lc = n0w + nc * 8 + cq;
            float* a4 = acc[mt][nc];
            *(float2*)(P + row0 * 128 + lc) = make_float2(a4[0], a4[1]);
            *(float2*)(P + row1 * 128 + lc) = make_float2(a4[2], a4[3]);
        }
    }
}

// ---------------------------------------------------------------------------
// K5: reduce split-K partials + row softmax.
// ---------------------------------------------------------------------------
__global__ void k_softmax() {
    int r = blockIdx.x;
    int gq = r >> 10;
    int rb = r & 1023;
    int b = rb >> 7;
    int cc = rb & 127;
    int d = threadIdx.x;

    const float* pf = &d_partial[0][0];
    size_t base = (size_t)((gq * 8 + b) * 16) * (CHN * CHN) + cc * 128 + d;
    float v = 0.f;
    #pragma unroll
    for (int s = 0; s < 16; s++) v += pf[base + (size_t)s * (CHN * CHN)];

    __shared__ float sm[4];
    __shared__ float ss[4];
    int lane = d & 31, wid = d >> 5;
    float m = v;
    #pragma unroll
    for (int off = 16; off; off >>= 1) m = fmaxf(m, __shfl_xor_sync(0xffffffffu, m, off));
    if (lane == 0) sm[wid] = m;
    __syncthreads();
    m = fmaxf(fmaxf(sm[0], sm[1]), fmaxf(sm[2], sm[3]));

    float e = expf(v - m);
    float sum = e;
    #pragma unroll
    for (int off = 16; off; off >>= 1) sum += __shfl_xor_sync(0xffffffffu, sum, off);
    if (lane == 0) ss[wid] = sum;
    __syncthreads();
    sum = ss[0] + ss[1] + ss[2] + ss[3];

    d_probs[gq][(b * 128 + cc) * 128 + d] = e / sum;
}

// ---------------------------------------------------------------------------
// K7: final linear fused with output permutation + residual (writes d_out).
// Tiling: CTA = (c4, b); p-rows = c4 + 128*w4 (w4 = 0..127); cols co = h4.
// out[b,c4,h4,w4] = acc[w4][h4] + lb[h4] + Fi + Fw  — one contiguous plane.
// Epilogue transposes acc via smem T[128][129] (conflict-free).
// grid (128, 8), block 256.
// ---------------------------------------------------------------------------
__global__ void __launch_bounds__(256, 1) k_final3(const float* lw, const float* lb,
                                                   const float* Fi, const float* Fw,
                                                   float* out) {
    extern __shared__ char dynsm[];
    __nv_bfloat16* sAH = (__nv_bfloat16*)(dynsm);
    __nv_bfloat16* sAL = (__nv_bfloat16*)(dynsm + 34816);
    __nv_bfloat16* sXH = (__nv_bfloat16*)(dynsm + 69632);
    __nv_bfloat16* sXL = (__nv_bfloat16*)(dynsm + 104448);

    const int tid = threadIdx.x;
    const int c4 = blockIdx.x;
    const int b = blockIdx.y;

    const int wid = tid >> 5, lane = tid & 31;
    const int m0w = (wid >> 1) << 5;
    const int n0w = (wid & 1) << 6;
    const int tle = lane >> 3, li = lane & 7;
    const uint32_t smem0 = s2u(dynsm);
    const uint32_t aoff = smem0 +
        (((uint32_t)(m0w + li + ((tle & 1) << 3)) * PADK + ((tle & 2) << 2)) << 1);
    const uint32_t boff = smem0 + 69632 +
        ((((uint32_t)(li + ((tle & 1) << 3))) * PADK + (uint32_t)n0w + ((tle & 2) << 2)) << 1);
    const uint32_t DA = 34816u;
    const uint32_t DB = 34816u;
    const uint32_t MSTEP = 16 * PADK * 2;

    float acc[2][8][4];
    #pragma unroll
    for (int i = 0; i < 2; i++)
        #pragma unroll
        for (int j = 0; j < 8; j++)
            #pragma unroll
            for (int q = 0; q < 4; q++) acc[i][j][q] = 0.f;

    #pragma unroll
    for (int half = 0; half < 2; half++) {
        const float* Ab = d_att[half] + (size_t)b * CHW;
        // A fill: row m = w4 -> att row p = c4 + 128*m
        #pragma unroll
        for (int it = 0; it < 16; it++) {
            int idx = tid + (it << 8);
            int m = idx >> 5, q = (idx & 31) << 2;
            float4 v = *(const float4*)(Ab + (size_t)(c4 + (m << 7)) * 128 + q);
            uint2 hi, lo;
            split4(v, hi, lo);
            *(uint2*)(sAH + m * PADK + q) = hi;
            *(uint2*)(sAL + m * PADK + q) = lo;
        }
        // B fill: lw[co][half*128 + k] transposed -> sX[k][co]
        #pragma unroll
        for (int it = 0; it < 16; it++) {
            int idx = tid + (it << 8);
            int co = idx >> 5, q = (idx & 31) << 2;
            float4 v = *(const float4*)(lw + co * 256 + half * 128 + q);
            float h0 = __bfloat162float(__float2bfloat16(v.x));
            float h1 = __bfloat162float(__float2bfloat16(v.y));
            float h2 = __bfloat162float(__float2bfloat16(v.z));
            float h3 = __bfloat162float(__float2bfloat16(v.w));
            sXH[(q + 0) * PADK + co] = __float2bfloat16(v.x);
            sXH[(q + 1) * PADK + co] = __float2bfloat16(v.y);
            sXH[(q + 2) * PADK + co] = __float2bfloat16(v.z);
            sXH[(q + 3) * PADK + co] = __float2bfloat16(v.w);
            sXL[(q + 0) * PADK + co] = __float2bfloat16(v.x - h0);
            sXL[(q + 1) * PADK + co] = __float2bfloat16(v.y - h1);
            sXL[(q + 2) * PADK + co] = __float2bfloat16(v.z - h2);
            sXL[(q + 3) * PADK + co] = __float2bfloat16(v.w - h3);
        }
        __syncthreads();

        #pragma unroll 2
        for (int ks = 0; ks < 8; ks++) {
            uint32_t aH[2][4], aL[2][4], bH[4][4], bL[4][4];
            uint32_t ab = aoff + ks * 32;
            ldsm4(aH[0], ab);
            ldsm4(aH[1], ab + MSTEP);
            ldsm4(aL[0], ab + DA);
            ldsm4(aL[1], ab + DA + MSTEP);
            uint32_t bb = boff + ks * MSTEP;
            #pragma unroll
            for (int c = 0; c < 4; c++) {
                ldsm4t(bH[c], bb + c * 32);
                ldsm4t(bL[c], bb + c * 32 + DB);
            }
            #pragma unroll
            for (int mt = 0; mt < 2; mt++) {
                #pragma unroll
                for (int nc = 0; nc < 8; nc++) {
                    const uint32_t* bh = &bH[nc >> 1][(nc & 1) << 1];
                    const uint32_t* bl = &bL[nc >> 1][(nc & 1) << 1];
                    mma16816(acc[mt][nc], aH[mt], bh);
                    mma16816(acc[mt][nc], aH[mt], bl);
                    mma16816(acc[mt][nc], aL[mt], bh);
                }
            }
        }
        __syncthreads();
    }

    // ---- epilogue: acc (+bias) -> T, transpose, add residual, write d_out ----
    float* T = (float*)(dynsm + 69632);   // 128 x 129 floats, reuses B region
    const int r = lane >> 2, cq = (lane & 3) << 1;
    #pragma unroll
    for (int mt = 0; mt < 2; mt++) {
        int row0 = m0w + mt * 16 + r;     // w4
        int row1 = row0 + 8;
        #pragma unroll
        for (int nc = 0; nc < 8; nc++) {
            int lc = n0w + nc * 8 + cq;   // h4
            float* a4 = acc[mt][nc];
            float b0 = lb[lc], b1 = lb[lc + 1];
            T[row0 * 129 + lc]     = a4[0] + b0;
            T[row0 * 129 + lc + 1] = a4[1] + b1;
            T[row1 * 129 + lc]     = a4[2] + b0;
            T[row1 * 129 + lc + 1] = a4[3] + b1;
        }
    }
    __syncthreads();

    const size_t obase = ((size_t)(b * 128 + c4)) << 14;   // *16384
    #pragma unroll 8
    for (int it = 0; it < 64; it++) {
        int idx = tid + (it << 8);        // = h4*128 + w4
        int h4 = idx >> 7, w4 = idx & 127;
        float v = T[w4 * 129 + h4];
        out[obase + idx] = v + Fi[obase + idx] + Fw[obase + idx];
    }
}

// ---------------------------------------------------------------------------
// Launch.  Inputs in setup_inputs() dict order (guard on in_sizes[5]).
// ---------------------------------------------------------------------------
extern "C" void kernel_launch(void* const* d_in, const int* in_sizes, int n_in,
                              void* d_out, int out_size) {
    (void)n_in; (void)out_size;
    const float* F_i = (const float*)d_in[0];
    const float* F_w = (const float*)d_in[1];

    const bool interleaved = (in_sizes[5] == 128);

    PtrArgs pa;
    pa.f[0] = F_i;
    pa.f[1] = F_w;
    pa.g[0] = (const float*)d_in[2];
    pa.g[1] = (const float*)d_in[3];

    int w_idx[6], b_idx[6], dw_idx[6], db_idx[6];
    if (interleaved) {
        for (int t = 0; t < 6; t++) {
            w_idx[t]  = 4 + 2 * t;
            b_idx[t]  = 5 + 2 * t;
            dw_idx[t] = 16 + 2 * t;
            db_idx[t] = 17 + 2 * t;
        }
    } else {
        for (int t = 0; t < 6; t++) {
            w_idx[t]  = 4 + t;
            b_idx[t]  = 10 + t;
            dw_idx[t] = 16 + t;
            db_idx[t] = 22 + t;
        }
    }
    DwArgs da;
    for (int t = 0; t < 6; t++) {
        pa.w[t]    = (const float*)d_in[w_idx[t]];
        pa.bias[t] = (const float*)d_in[b_idx[t]];
        da.w[t]    = (const float*)d_in[dw_idx[t]];
        da.b[t]    = (const float*)d_in[db_idx[t]];
    }

    cudaFuncSetAttribute(k_mma<0>, cudaFuncAttributeMaxDynamicSharedMemorySize, SMTOT2);
    cudaFuncSetAttribute(k_mma<1>, cudaFuncAttributeMaxDynamicSharedMemorySize, SMTOT2);
    cudaFuncSetAttribute(k_final3, cudaFuncAttributeMaxDynamicSharedMemorySize, SMTOT2);

    // 0) weight*gamma + row sums
    k_prep<<<6 * 128, 128>>>(pa);
    // 1) LN stats
    k_ln<<<dim3(BATCH * HWX / 256, 2), 256>>>(pa);
    // 2) fused LN + 1x1 conv on HMMA (pipelined, 4 tiles/CTA)
    k_mma<0><<<dim3(48, 32), 256, SMTOT2>>>(pa);
    // 3) depthwise 3x3 (register sliding window)
    k_dw2<<<dim3(4, 6144), dim3(32, 4)>>>(da);
    // 4) QK logits split-K on HMMA (LDG-ahead)
    k_qk2<<<dim3(16, 16), 256>>>();
    // 5) reduce + softmax
    k_softmax<<<2048, 128>>>();
    // 6) AV GEMMs on HMMA (pipelined, 4 tiles/CTA)
    k_mma<1><<<dim3(16, 32), 256, SMTOT2>>>(pa);
    // 7) final linear + permutation + residual (writes d_out directly)
    k_final3<<<dim3(128, 8), 256, SMTOT2>>>((const float*)d_in[28],
                                            (const float*)d_in[29],
                                            F_i, F_w, (float*)d_out);
}

// round 17
// speedup vs baseline: 1.9653x; 1.0749x over previous
#include <cuda_runtime.h>
#include <cuda_bf16.h>
#include <math.h>
#include <stdint.h>

// Problem dims (fixed by the reference)
#define BATCH 8
#define CHN   128
#define HWX   16384                 // 128*128
#define CHW   (CHN*HWX)             // 2097152
#define NPT   (BATCH*CHW)           // 16777216 elements per tensor

// ---------------------------------------------------------------------------
// Scratch (static device globals: allocation-free per harness rules)
// ---------------------------------------------------------------------------
__device__ float d_tmp[6][NPT];                  // conv1x1 outputs (pre-depthwise)
__device__ __nv_bfloat16 d_qh[6][NPT];           // dw outputs, hi plane
__device__ __nv_bfloat16 d_ql[6][NPT];           // dw outputs, lo plane
__device__ __nv_bfloat16 d_ath[2][NPT];          // AV outputs, hi plane
__device__ __nv_bfloat16 d_atl[2][NPT];          // AV outputs, lo plane
__device__ float d_mean[2][BATCH*HWX];
__device__ float d_rstd[2][BATCH*HWX];
__device__ __nv_bfloat16 d_wgh[6][CHN*CHN];      // Wg hi/lo planes
__device__ __nv_bfloat16 d_wgl[6][CHN*CHN];
__device__ float d_Ssum[6][CHN];                 // row sums of Wg
__device__ __nv_bfloat16 d_ph[2][BATCH*CHN*CHN]; // softmax hi/lo planes
__device__ __nv_bfloat16 d_pl[2][BATCH*CHN*CHN];
__device__ float d_partial[144][CHN*CHN];        // QK split-K partials (9 slabs)
__device__ __nv_bfloat16 d_lwh[256*CHN];         // lw transposed [k][co] hi/lo
__device__ __nv_bfloat16 d_lwl[256*CHN];

struct PtrArgs {
    const float* f[2];      // F_i, F_w
    const float* g[2];      // g1, g2
    const float* w[6];      // qw1,kw1,vw1,qw2,kw2,vw2
    const float* bias[6];   // conv biases
};
struct DwArgs {
    const float* w[6];
    const float* b[6];
};

// ---------------------------------------------------------------------------
// Helpers (compute_103-safe: ldmatrix + mma.sync only, no tcgen05)
// ---------------------------------------------------------------------------
__device__ __forceinline__ uint32_t s2u(const void* p) {
    uint32_t r;
    asm("{ .reg .u64 t; cvta.to.shared.u64 t, %1; cvt.u32.u64 %0, t; }" : "=r"(r) : "l"(p));
    return r;
}
__device__ __forceinline__ uint32_t pack_bf16(float a, float b) {
    __nv_bfloat162 t = __floats2bfloat162_rn(a, b);
    return *(uint32_t*)&t;
}
__device__ __forceinline__ void ldsm4(uint32_t* r, uint32_t addr) {
    asm volatile("ldmatrix.sync.aligned.m8n8.x4.shared.b16 {%0,%1,%2,%3}, [%4];"
                 : "=r"(r[0]), "=r"(r[1]), "=r"(r[2]), "=r"(r[3]) : "r"(addr));
}
__device__ __forceinline__ void ldsm4t(uint32_t* r, uint32_t addr) {
    asm volatile("ldmatrix.sync.aligned.m8n8.x4.trans.shared.b16 {%0,%1,%2,%3}, [%4];"
                 : "=r"(r[0]), "=r"(r[1]), "=r"(r[2]), "=r"(r[3]) : "r"(addr));
}
// A-operand via trans-ldmatrix from [k][m] smem: fragment order needs {r0,r2,r1,r3}
__device__ __forceinline__ void ldsm4t_A(uint32_t* a, uint32_t addr) {
    uint32_t t[4];
    ldsm4t(t, addr);
    a[0] = t[0]; a[1] = t[2]; a[2] = t[1]; a[3] = t[3];
}
__device__ __forceinline__ void mma16816(float* d, const uint32_t* a, const uint32_t* b) {
    asm volatile(
        "mma.sync.aligned.m16n8k16.row.col.f32.bf16.bf16.f32 "
        "{%0,%1,%2,%3}, {%4,%5,%6,%7}, {%8,%9}, {%0,%1,%2,%3};"
        : "+f"(d[0]), "+f"(d[1]), "+f"(d[2]), "+f"(d[3])
        : "r"(a[0]), "r"(a[1]), "r"(a[2]), "r"(a[3]), "r"(b[0]), "r"(b[1]));
}
__device__ __forceinline__ void split4(float4 v, uint2& hi, uint2& lo) {
    float h0 = __bfloat162float(__float2bfloat16(v.x));
    float h1 = __bfloat162float(__float2bfloat16(v.y));
    float h2 = __bfloat162float(__float2bfloat16(v.z));
    float h3 = __bfloat162float(__float2bfloat16(v.w));
    hi = make_uint2(pack_bf16(v.x, v.y), pack_bf16(v.z, v.w));
    lo = make_uint2(pack_bf16(v.x - h0, v.y - h1), pack_bf16(v.z - h2, v.w - h3));
}
__device__ __forceinline__ void split2(float a, float b, uint32_t& hi, uint32_t& lo) {
    float ha = __bfloat162float(__float2bfloat16(a));
    float hb = __bfloat162float(__float2bfloat16(b));
    hi = pack_bf16(a, b);
    lo = pack_bf16(a - ha, b - hb);
}

#define PADK 136

// ---------------------------------------------------------------------------
// K0: Wg = W * g (split planes), Ssum = row sums of Wg.
// ---------------------------------------------------------------------------
__global__ void k_prep(PtrArgs pa) {
    int t = blockIdx.x >> 7;
    int o = blockIdx.x & 127;
    int c = threadIdx.x;
    const float* gsrc = pa.g[t < 3 ? 0 : 1];
    float v = pa.w[t][o * CHN + c] * gsrc[c];
    float h = __bfloat162float(__float2bfloat16(v));
    d_wgh[t][o * CHN + c] = __float2bfloat16(v);
    d_wgl[t][o * CHN + c] = __float2bfloat16(v - h);
    float s = v;
    #pragma unroll
    for (int off = 16; off; off >>= 1) s += __shfl_xor_sync(0xffffffffu, s, off);
    __shared__ float sm[4];
    if ((c & 31) == 0) sm[c >> 5] = s;
    __syncthreads();
    if (c == 0) d_Ssum[t][o] = sm[0] + sm[1] + sm[2] + sm[3];
}

// K0b: lw transposed + split into [k][co] planes.
__global__ void k_prepLW(const float* lw) {
    int k = blockIdx.x;          // 0..255
    int co = threadIdx.x;        // 0..127
    float v = lw[co * 256 + k];
    float h = __bfloat162float(__float2bfloat16(v));
    d_lwh[k * 128 + co] = __float2bfloat16(v);
    d_lwl[k * 128 + co] = __float2bfloat16(v - h);
}

// ---------------------------------------------------------------------------
// K1: LayerNorm statistics per pixel.
// ---------------------------------------------------------------------------
__global__ void k_ln(PtrArgs pa) {
    int s = blockIdx.y;
    int p = blockIdx.x * 256 + threadIdx.x;
    int b = p >> 14;
    int hw = p & 16383;
    const float* x = pa.f[s] + (size_t)b * CHW + hw;
    float s1 = 0.f, s2 = 0.f;
    #pragma unroll 16
    for (int c = 0; c < CHN; c++) {
        float v = x[(size_t)c * HWX];
        s1 += v;
        s2 += v * v;
    }
    float m = s1 * (1.0f / CHN);
    float var = s2 * (1.0f / CHN) - m * m;
    d_mean[s][p] = m;
    d_rstd[s][p] = rsqrtf(var + 1e-5f);
}

// ---------------------------------------------------------------------------
// K2: conv1x1 on HMMA, persistent A + pipelined X (f32 source, split in-kernel).
// A fill from pre-split Wg planes. LN epilogue -> d_tmp (f32).
// ---------------------------------------------------------------------------
#define NT 4
#define SMTOT2 139264

__global__ void __launch_bounds__(256, 1) k_conv(PtrArgs pa) {
    extern __shared__ char dynsm[];
    __nv_bfloat16* sAH = (__nv_bfloat16*)(dynsm);
    __nv_bfloat16* sAL = (__nv_bfloat16*)(dynsm + 34816);

    const int tid = threadIdx.x;
    const int z = blockIdx.x;
    int t = z % 6, b = z / 6;
    int s = (t < 3) ? 0 : 1;
    const __nv_bfloat16* Ahp = d_wgh[t];
    const __nv_bfloat16* Alp = d_wgl[t];
    const float* X = pa.f[s] + (size_t)b * CHW;
    float* Y = d_tmp[t] + (size_t)b * CHW;
    const float* meanp = d_mean[s] + b * HWX;
    const float* rstdp = d_rstd[s] + b * HWX;
    const float* Sp = d_Ssum[t];
    const float* biasp = pa.bias[t];

    // ---- A fill (copies from pre-split planes) ----
    #pragma unroll
    for (int it = 0; it < 16; it++) {
        int idx = tid + (it << 8);
        int m = idx >> 5, q = (idx & 31) << 2;
        *(uint2*)(sAH + m * PADK + q) = *(const uint2*)(Ahp + m * CHN + q);
        *(uint2*)(sAL + m * PADK + q) = *(const uint2*)(Alp + m * CHN + q);
    }

    const int wid = tid >> 5, lane = tid & 31;
    const int m0w = (wid >> 1) << 5;
    const int n0w = (wid & 1) << 6;
    const int tle = lane >> 3, li = lane & 7;
    const uint32_t smem0 = s2u(dynsm);
    const uint32_t aoff = smem0 +
        (((uint32_t)(m0w + li + ((tle & 1) << 3)) * PADK + ((tle & 2) << 2)) << 1);
    const uint32_t brow =
        (((uint32_t)(li + ((tle & 1) << 3)) * PADK + (uint32_t)n0w + ((tle & 2) << 2)) << 1);
    const uint32_t DA = 34816u;
    const uint32_t DXB = 17408u;
    const uint32_t MSTEP = 16 * PADK * 2;

    const int rowf = tid >> 5;
    const int qf = (tid & 31) << 2;

    float acc[2][8][4];
    #pragma unroll
    for (int i = 0; i < 2; i++)
        #pragma unroll
        for (int j = 0; j < 8; j++)
            #pragma unroll
            for (int q = 0; q < 4; q++) acc[i][j][q] = 0.f;

    float4 R[8];
    {
        int n00 = (blockIdx.y * NT) << 7;
        const float* Xb = X + (size_t)rowf * HWX + n00 + qf;
        #pragma unroll
        for (int it = 0; it < 8; it++)
            R[it] = *(const float4*)(Xb + (size_t)(it * 8) * HWX);
    }

    for (int j = 0; j < NT; j++) {
        const int n0 = ((blockIdx.y * NT + j) << 7);
        #pragma unroll
        for (int h = 0; h < 2; h++) {
            {
                __nv_bfloat16* XH = (__nv_bfloat16*)(dynsm + 69632 + h * 34816);
                __nv_bfloat16* XL = XH + 8704;
                #pragma unroll
                for (int it = 0; it < 8; it++) {
                    int row = rowf + it * 8;
                    uint2 hi, lo;
                    split4(R[it], hi, lo);
                    *(uint2*)(XH + row * PADK + qf) = hi;
                    *(uint2*)(XL + row * PADK + qf) = lo;
                }
            }
            if (!((j == NT - 1) && (h == 1))) {
                int jn = (h == 0) ? j : j + 1;
                int hn = (h == 0) ? 1 : 0;
                int n0n = ((blockIdx.y * NT + jn) << 7);
                const float* Xb = X + (size_t)(hn * 64 + rowf) * HWX + n0n + qf;
                #pragma unroll
                for (int it = 0; it < 8; it++)
                    R[it] = *(const float4*)(Xb + (size_t)(it * 8) * HWX);
            }
            __syncthreads();
            uint32_t abase = aoff + h * 128;
            uint32_t bbase = smem0 + 69632 + h * 34816 + brow;
            #pragma unroll
            for (int ks = 0; ks < 4; ks++) {
                uint32_t aH[2][4], aL[2][4], bH[4][4], bL[4][4];
                uint32_t ab = abase + ks * 32;
                ldsm4(aH[0], ab);
                ldsm4(aH[1], ab + MSTEP);
                ldsm4(aL[0], ab + DA);
                ldsm4(aL[1], ab + DA + MSTEP);
                uint32_t bb = bbase + ks * MSTEP;
                #pragma unroll
                for (int c = 0; c < 4; c++) {
                    ldsm4t(bH[c], bb + c * 32);
                    ldsm4t(bL[c], bb + c * 32 + DXB);
                }
                #pragma unroll
                for (int mt = 0; mt < 2; mt++) {
                    #pragma unroll
                    for (int nc = 0; nc < 8; nc++) {
                        const uint32_t* bh = &bH[nc >> 1][(nc & 1) << 1];
                        const uint32_t* bl = &bL[nc >> 1][(nc & 1) << 1];
                        mma16816(acc[mt][nc], aH[mt], bh);
                        mma16816(acc[mt][nc], aH[mt], bl);
                        mma16816(acc[mt][nc], aL[mt], bh);
                    }
                }
            }
        }

        const int r = lane >> 2, cq = (lane & 3) << 1;
        #pragma unroll
        for (int mt = 0; mt < 2; mt++) {
            int row0 = m0w + mt * 16 + r;
            int row1 = row0 + 8;
            float S0 = Sp[row0], B0 = biasp[row0], S1 = Sp[row1], B1 = biasp[row1];
            float* y0 = Y + (size_t)row0 * HWX + n0;
            float* y1 = Y + (size_t)row1 * HWX + n0;
            #pragma unroll
            for (int nc = 0; nc < 8; nc++) {
                int lc = n0w + nc * 8 + cq;
                float* a4 = acc[mt][nc];
                float rs0 = rstdp[n0 + lc], rs1 = rstdp[n0 + lc + 1];
                float ms0 = meanp[n0 + lc] * rs0, ms1 = meanp[n0 + lc + 1] * rs1;
                *(float2*)(y0 + lc) = make_float2(fmaf(a4[0], rs0, fmaf(-S0, ms0, B0)),
                                                  fmaf(a4[1], rs1, fmaf(-S0, ms1, B0)));
                *(float2*)(y1 + lc) = make_float2(fmaf(a4[2], rs0, fmaf(-S1, ms0, B1)),
                                                  fmaf(a4[3], rs1, fmaf(-S1, ms1, B1)));
                a4[0] = a4[1] = a4[2] = a4[3] = 0.f;
            }
        }
    }
}

// ---------------------------------------------------------------------------
// K3: depthwise 3x3, register sliding-window; writes split hi/lo bf16 planes.
// ---------------------------------------------------------------------------
__global__ void __launch_bounds__(128) k_dw2(DwArgs da) {
    int zz = blockIdx.y;               // t*1024 + (b*128+c)
    int t = zz >> 10;
    int pl = zz & 1023;
    int c = pl & 127;
    const float* wd = da.w[t] + c * 9;
    float w00 = wd[0], w01 = wd[1], w02 = wd[2];
    float w10 = wd[3], w11 = wd[4], w12 = wd[5];
    float w20 = wd[6], w21 = wd[7], w22 = wd[8];
    float bias = da.b[t][c];
    const float* sp = d_tmp[t] + (size_t)pl * HWX;
    __nv_bfloat16* oph = d_qh[t] + (size_t)pl * HWX;
    __nv_bfloat16* opl = d_ql[t] + (size_t)pl * HWX;

    const int tx = threadIdx.x;
    const int x0 = tx << 2;
    const int h0 = blockIdx.x * 32 + threadIdx.y * 8;

    float4 C[3];
    float L[3], R[3];
    #define LOADROW(hh, s) do { \
        int _h = (hh); \
        if ((unsigned)_h < 128u) { \
            const float* rp = sp + _h * 128; \
            C[s] = *(const float4*)(rp + x0); \
            L[s] = (tx > 0) ? rp[x0 - 1] : 0.f; \
            R[s] = (tx < 31) ? rp[x0 + 4] : 0.f; \
        } else { C[s] = make_float4(0.f, 0.f, 0.f, 0.f); L[s] = 0.f; R[s] = 0.f; } \
    } while (0)

    LOADROW(h0 - 1, 0);
    LOADROW(h0, 1);
    #pragma unroll
    for (int y = 0; y < 8; y++) {
        LOADROW(h0 + y + 1, (y + 2) % 3);
        const int i0 = y % 3, i1 = (y + 1) % 3, i2 = (y + 2) % 3;
        float4 o;
        o.x = bias;
        o.x = fmaf(w00, L[i0],   fmaf(w01, C[i0].x, fmaf(w02, C[i0].y, o.x)));
        o.x = fmaf(w10, L[i1],   fmaf(w11, C[i1].x, fmaf(w12, C[i1].y, o.x)));
        o.x = fmaf(w20, L[i2],   fmaf(w21, C[i2].x, fmaf(w22, C[i2].y, o.x)));
        o.y = bias;
        o.y = fmaf(w00, C[i0].x, fmaf(w01, C[i0].y, fmaf(w02, C[i0].z, o.y)));
        o.y = fmaf(w10, C[i1].x, fmaf(w11, C[i1].y, fmaf(w12, C[i1].z, o.y)));
        o.y = fmaf(w20, C[i2].x, fmaf(w21, C[i2].y, fmaf(w22, C[i2].z, o.y)));
        o.z = bias;
        o.z = fmaf(w00, C[i0].y, fmaf(w01, C[i0].z, fmaf(w02, C[i0].w, o.z)));
        o.z = fmaf(w10, C[i1].y, fmaf(w11, C[i1].z, fmaf(w12, C[i1].w, o.z)));
        o.z = fmaf(w20, C[i2].y, fmaf(w21, C[i2].z, fmaf(w22, C[i2].w, o.z)));
        o.w = bias;
        o.w = fmaf(w00, C[i0].z, fmaf(w01, C[i0].w, fmaf(w02, R[i0], o.w)));
        o.w = fmaf(w10, C[i1].z, fmaf(w11, C[i1].w, fmaf(w12, R[i1], o.w)));
        o.w = fmaf(w20, C[i2].z, fmaf(w21, C[i2].w, fmaf(w22, R[i2], o.w)));
        uint2 hi, lo;
        split4(o, hi, lo);
        *(uint2*)(oph + (h0 + y) * 128 + x0) = hi;
        *(uint2*)(opl + (h0 + y) * 128 + x0) = lo;
    }
    #undef LOADROW
}

// ---------------------------------------------------------------------------
// K4: QK logits, split-K (9 unequal slabs = 144 CTAs, 1 full wave).
// Fills are pure copies from pre-split planes.
// ---------------------------------------------------------------------------
__global__ void __launch_bounds__(256) k_qk3() {
    __shared__ __nv_bfloat16 sQH[32 * PADK], sQL[32 * PADK];
    __shared__ __nv_bfloat16 sKH[32 * PADK], sKL[32 * PADK];
    const int slab = blockIdx.x;       // 0..8
    const int z = blockIdx.y;
    const int gq = z >> 3, b = z & 7;
    const int qi = (gq == 0) ? 0 : 3, ki = (gq == 0) ? 4 : 1;
    const __nv_bfloat16* Qh = d_qh[qi] + (size_t)b * CHW;
    const __nv_bfloat16* Ql = d_ql[qi] + (size_t)b * CHW;
    const __nv_bfloat16* Kh = d_qh[ki] + (size_t)b * CHW;
    const __nv_bfloat16* Kl = d_ql[ki] + (size_t)b * CHW;
    float* P = d_partial[z * 9 + slab];

    const int kb = slab * 1824;
    const int nch = (slab == 8) ? 56 : 57;    // chunks of 32 k-rows

    const int tid = threadIdx.x, wid = tid >> 5, lane = tid & 31;
    const int m0w = (wid >> 1) << 5;
    const int n0w = (wid & 1) << 6;
    const int tle = lane >> 3, li = lane & 7;
    const uint32_t rowpart = (uint32_t)(li + ((tle & 1) << 3)) * PADK + ((tle & 2) << 2);
    const uint32_t qHa = s2u(sQH) + (rowpart << 1);
    const uint32_t qLa = s2u(sQL) + (rowpart << 1);
    const uint32_t kHa = s2u(sKH) + (rowpart << 1);
    const uint32_t kLa = s2u(sKL) + (rowpart << 1);
    const uint32_t HSTEP = 16 * PADK * 2;

    const int rowc = tid >> 4;          // 0..15 (fill row within 16-row group)
    const int sg = tid & 15;            // 16B segment within a row

    float acc[2][8][4];
    #pragma unroll
    for (int i = 0; i < 2; i++)
        #pragma unroll
        for (int j = 0; j < 8; j++)
            #pragma unroll
            for (int q = 0; q < 4; q++) acc[i][j][q] = 0.f;

    uint4 RqH[2], RqL[2], RkH[2], RkL[2];
    #pragma unroll
    for (int it = 0; it < 2; it++) {
        size_t g = (size_t)(kb + rowc + it * 16) * 128 + sg * 8;
        RqH[it] = *(const uint4*)(Qh + g);
        RqL[it] = *(const uint4*)(Ql + g);
        RkH[it] = *(const uint4*)(Kh + g);
        RkL[it] = *(const uint4*)(Kl + g);
    }

    for (int c = 0; c < nch; c++) {
        #pragma unroll
        for (int it = 0; it < 2; it++) {
            int row = rowc + it * 16;
            *(uint4*)(sQH + row * PADK + sg * 8) = RqH[it];
            *(uint4*)(sQL + row * PADK + sg * 8) = RqL[it];
            *(uint4*)(sKH + row * PADK + sg * 8) = RkH[it];
            *(uint4*)(sKL + row * PADK + sg * 8) = RkL[it];
        }
        if (c + 1 < nch) {
            #pragma unroll
            for (int it = 0; it < 2; it++) {
                size_t g = (size_t)(kb + (c + 1) * 32 + rowc + it * 16) * 128 + sg * 8;
                RqH[it] = *(const uint4*)(Qh + g);
                RqL[it] = *(const uint4*)(Ql + g);
                RkH[it] = *(const uint4*)(Kh + g);
                RkL[it] = *(const uint4*)(Kl + g);
            }
        }
        __syncthreads();

        #pragma unroll
        for (int half = 0; half < 2; half++) {
            uint32_t roff = half * HSTEP;
            uint32_t aH[2][4], aL[2][4], bH[4][4], bL[4][4];
            #pragma unroll
            for (int mt = 0; mt < 2; mt++) {
                uint32_t mb = (uint32_t)(m0w + mt * 16) * 2;
                ldsm4t_A(aH[mt], qHa + roff + mb);
                ldsm4t_A(aL[mt], qLa + roff + mb);
            }
            #pragma unroll
            for (int cc = 0; cc < 4; cc++) {
                uint32_t nb = (uint32_t)(n0w + cc * 16) * 2;
                ldsm4t(bH[cc], kHa + roff + nb);
                ldsm4t(bL[cc], kLa + roff + nb);
            }
            #pragma unroll
            for (int mt = 0; mt < 2; mt++) {
                #pragma unroll
                for (int nc = 0; nc < 8; nc++) {
                    const uint32_t* bh = &bH[nc >> 1][(nc & 1) << 1];
                    const uint32_t* bl = &bL[nc >> 1][(nc & 1) << 1];
                    mma16816(acc[mt][nc], aH[mt], bh);
                    mma16816(acc[mt][nc], aH[mt], bl);
                    mma16816(acc[mt][nc], aL[mt], bh);
                }
            }
        }
        __syncthreads();
    }

    const int r = lane >> 2, cq = (lane & 3) << 1;
    #pragma unroll
    for (int mt = 0; mt < 2; mt++) {
        int row0 = m0w + mt * 16 + r;
        int row1 = row0 + 8;
        #pragma unroll
        for (int nc = 0; nc < 8; nc++) {
            int lc = n0w + nc * 8 + cq;
            float* a4 = acc[mt][nc];
            *(float2*)(P + row0 * 128 + lc) = make_float2(a4[0], a4[1]);
            *(float2*)(P + row1 * 128 + lc) = make_float2(a4[2], a4[3]);
        }
    }
}

// ---------------------------------------------------------------------------
// K5: reduce 9 split-K partials + row softmax -> split probs planes.
// ---------------------------------------------------------------------------
__global__ void k_softmax() {
    int r = blockIdx.x;
    int gq = r >> 10;
    int rb = r & 1023;
    int b = rb >> 7;
    int cc = rb & 127;
    int d = threadIdx.x;

    const float* pf = &d_partial[0][0];
    size_t base = (size_t)((gq * 8 + b) * 9) * (CHN * CHN) + cc * 128 + d;
    float v = 0.f;
    #pragma unroll
    for (int s = 0; s < 9; s++) v += pf[base + (size_t)s * (CHN * CHN)];

    __shared__ float sm[4];
    __shared__ float ss[4];
    int lane = d & 31, wid = d >> 5;
    float m = v;
    #pragma unroll
    for (int off = 16; off; off >>= 1) m = fmaxf(m, __shfl_xor_sync(0xffffffffu, m, off));
    if (lane == 0) sm[wid] = m;
    __syncthreads();
    m = fmaxf(fmaxf(sm[0], sm[1]), fmaxf(sm[2], sm[3]));

    float e = expf(v - m);
    float sum = e;
    #pragma unroll
    for (int off = 16; off; off >>= 1) sum += __shfl_xor_sync(0xffffffffu, sum, off);
    if (lane == 0) ss[wid] = sum;
    __syncthreads();
    sum = ss[0] + ss[1] + ss[2] + ss[3];

    float p = e / sum;
    float h = __bfloat162float(__float2bfloat16(p));
    int oi = (b * 128 + cc) * 128 + d;
    d_ph[gq][oi] = __float2bfloat16(p);
    d_pl[gq][oi] = __float2bfloat16(p - h);
}

// ---------------------------------------------------------------------------
// K6: AV GEMM on HMMA; A and X fills are copies from pre-split planes;
// epilogue writes split d_att planes.
// ---------------------------------------------------------------------------
__global__ void __launch_bounds__(256, 1) k_av() {
    extern __shared__ char dynsm[];
    __nv_bfloat16* sAH = (__nv_bfloat16*)(dynsm);
    __nv_bfloat16* sAL = (__nv_bfloat16*)(dynsm + 34816);

    const int tid = threadIdx.x;
    const int z = blockIdx.x;
    int gq = z & 1, b = z >> 1;
    int vi = (gq == 0) ? 5 : 2;
    const __nv_bfloat16* Ahp = d_ph[gq] + b * (CHN * CHN);
    const __nv_bfloat16* Alp = d_pl[gq] + b * (CHN * CHN);
    const __nv_bfloat16* Xh = d_qh[vi] + (size_t)b * CHW;
    const __nv_bfloat16* Xl = d_ql[vi] + (size_t)b * CHW;
    __nv_bfloat16* Yh = d_ath[gq] + (size_t)b * CHW;
    __nv_bfloat16* Yl = d_atl[gq] + (size_t)b * CHW;

    #pragma unroll
    for (int it = 0; it < 16; it++) {
        int idx = tid + (it << 8);
        int m = idx >> 5, q = (idx & 31) << 2;
        *(uint2*)(sAH + m * PADK + q) = *(const uint2*)(Ahp + m * CHN + q);
        *(uint2*)(sAL + m * PADK + q) = *(const uint2*)(Alp + m * CHN + q);
    }

    const int wid = tid >> 5, lane = tid & 31;
    const int m0w = (wid >> 1) << 5;
    const int n0w = (wid & 1) << 6;
    const int tle = lane >> 3, li = lane & 7;
    const uint32_t smem0 = s2u(dynsm);
    const uint32_t aoff = smem0 +
        (((uint32_t)(m0w + li + ((tle & 1) << 3)) * PADK + ((tle & 2) << 2)) << 1);
    const uint32_t brow =
        (((uint32_t)(li + ((tle & 1) << 3)) * PADK + (uint32_t)n0w + ((tle & 2) << 2)) << 1);
    const uint32_t DA = 34816u;
    const uint32_t DXB = 17408u;
    const uint32_t MSTEP = 16 * PADK * 2;

    const int rowc = tid >> 4;      // 0..15
    const int sg = tid & 15;

    float acc[2][8][4];
    #pragma unroll
    for (int i = 0; i < 2; i++)
        #pragma unroll
        for (int j = 0; j < 8; j++)
            #pragma unroll
            for (int q = 0; q < 4; q++) acc[i][j][q] = 0.f;

    uint4 Rh[4], Rl[4];
    {
        int n00 = (blockIdx.y * NT) << 7;
        #pragma unroll
        for (int it = 0; it < 4; it++) {
            size_t g = (size_t)(rowc + it * 16) * HWX + n00 + sg * 8;
            Rh[it] = *(const uint4*)(Xh + g);
            Rl[it] = *(const uint4*)(Xl + g);
        }
    }

    for (int j = 0; j < NT; j++) {
        const int n0 = ((blockIdx.y * NT + j) << 7);
        #pragma unroll
        for (int h = 0; h < 2; h++) {
            {
                __nv_bfloat16* XH = (__nv_bfloat16*)(dynsm + 69632 + h * 34816);
                __nv_bfloat16* XL = XH + 8704;
                #pragma unroll
                for (int it = 0; it < 4; it++) {
                    int row = rowc + it * 16;
                    *(uint4*)(XH + row * PADK + sg * 8) = Rh[it];
                    *(uint4*)(XL + row * PADK + sg * 8) = Rl[it];
                }
            }
            if (!((j == NT - 1) && (h == 1))) {
                int jn = (h == 0) ? j : j + 1;
                int hn = (h == 0) ? 1 : 0;
                int n0n = ((blockIdx.y * NT + jn) << 7);
                #pragma unroll
                for (int it = 0; it < 4; it++) {
                    size_t g = (size_t)(hn * 64 + rowc + it * 16) * HWX + n0n + sg * 8;
                    Rh[it] = *(const uint4*)(Xh + g);
                    Rl[it] = *(const uint4*)(Xl + g);
                }
            }
            __syncthreads();
            uint32_t abase = aoff + h * 128;
            uint32_t bbase = smem0 + 69632 + h * 34816 + brow;
            #pragma unroll
            for (int ks = 0; ks < 4; ks++) {
                uint32_t aH[2][4], aL[2][4], bH[4][4], bL[4][4];
                uint32_t ab = abase + ks * 32;
                ldsm4(aH[0], ab);
                ldsm4(aH[1], ab + MSTEP);
                ldsm4(aL[0], ab + DA);
                ldsm4(aL[1], ab + DA + MSTEP);
                uint32_t bb = bbase + ks * MSTEP;
                #pragma unroll
                for (int c = 0; c < 4; c++) {
                    ldsm4t(bH[c], bb + c * 32);
                    ldsm4t(bL[c], bb + c * 32 + DXB);
                }
                #pragma unroll
                for (int mt = 0; mt < 2; mt++) {
                    #pragma unroll
                    for (int nc = 0; nc < 8; nc++) {
                        const uint32_t* bh = &bH[nc >> 1][(nc & 1) << 1];
                        const uint32_t* bl = &bL[nc >> 1][(nc & 1) << 1];
                        mma16816(acc[mt][nc], aH[mt], bh);
                        mma16816(acc[mt][nc], aH[mt], bl);
                        mma16816(acc[mt][nc], aL[mt], bh);
                    }
                }
            }
        }

        const int r = lane >> 2, cq = (lane & 3) << 1;
        #pragma unroll
        for (int mt = 0; mt < 2; mt++) {
            int row0 = m0w + mt * 16 + r;
            int row1 = row0 + 8;
            size_t o0 = (size_t)row0 * HWX + n0;
            size_t o1 = (size_t)row1 * HWX + n0;
            #pragma unroll
            for (int nc = 0; nc < 8; nc++) {
                int lc = n0w + nc * 8 + cq;
                float* a4 = acc[mt][nc];
                uint32_t hi, lo;
                split2(a4[0], a4[1], hi, lo);
                *(uint32_t*)(Yh + o0 + lc) = hi;
                *(uint32_t*)(Yl + o0 + lc) = lo;
                split2(a4[2], a4[3], hi, lo);
                *(uint32_t*)(Yh + o1 + lc) = hi;
                *(uint32_t*)(Yl + o1 + lc) = lo;
                a4[0] = a4[1] = a4[2] = a4[3] = 0.f;
            }
        }
    }
}

// ---------------------------------------------------------------------------
// K7: final linear fused with output permutation + residual (writes d_out).
// A and B fills are copies from pre-split planes.
// ---------------------------------------------------------------------------
__global__ void __launch_bounds__(256, 1) k_final3(const float* lb,
                                                   const float* Fi, const float* Fw,
                                                   float* out) {
    extern __shared__ char dynsm[];
    __nv_bfloat16* sAH = (__nv_bfloat16*)(dynsm);
    __nv_bfloat16* sAL = (__nv_bfloat16*)(dynsm + 34816);
    __nv_bfloat16* sXH = (__nv_bfloat16*)(dynsm + 69632);
    __nv_bfloat16* sXL = (__nv_bfloat16*)(dynsm + 104448);

    const int tid = threadIdx.x;
    const int c4 = blockIdx.x;
    const int b = blockIdx.y;

    const int wid = tid >> 5, lane = tid & 31;
    const int m0w = (wid >> 1) << 5;
    const int n0w = (wid & 1) << 6;
    const int tle = lane >> 3, li = lane & 7;
    const uint32_t smem0 = s2u(dynsm);
    const uint32_t aoff = smem0 +
        (((uint32_t)(m0w + li + ((tle & 1) << 3)) * PADK + ((tle & 2) << 2)) << 1);
    const uint32_t boff = smem0 + 69632 +
        ((((uint32_t)(li + ((tle & 1) << 3))) * PADK + (uint32_t)n0w + ((tle & 2) << 2)) << 1);
    const uint32_t DA = 34816u;
    const uint32_t DB = 34816u;
    const uint32_t MSTEP = 16 * PADK * 2;

    const int rowc = tid >> 4;          // 0..15
    const int sg = tid & 15;

    float acc[2][8][4];
    #pragma unroll
    for (int i = 0; i < 2; i++)
        #pragma unroll
        for (int j = 0; j < 8; j++)
            #pragma unroll
            for (int q = 0; q < 4; q++) acc[i][j][q] = 0.f;

    #pragma unroll
    for (int half = 0; half < 2; half++) {
        const __nv_bfloat16* Ath = d_ath[half] + (size_t)b * CHW;
        const __nv_bfloat16* Atl = d_atl[half] + (size_t)b * CHW;
        // A fill: row m = w4 -> raw offset (c4 + 128*m)*128
        #pragma unroll
        for (int it = 0; it < 8; it++) {
            int m = rowc + it * 16;
            size_t g = (size_t)(c4 + (m << 7)) * 128 + sg * 8;
            *(uint4*)(sAH + m * PADK + sg * 8) = *(const uint4*)(Ath + g);
            *(uint4*)(sAL + m * PADK + sg * 8) = *(const uint4*)(Atl + g);
        }
        // B fill: pre-transposed lw planes [k][co]
        #pragma unroll
        for (int it = 0; it < 8; it++) {
            int k = rowc + it * 16;
            size_t g = (size_t)(half * 128 + k) * 128 + sg * 8;
            *(uint4*)(sXH + k * PADK + sg * 8) = *(const uint4*)(d_lwh + g);
            *(uint4*)(sXL + k * PADK + sg * 8) = *(const uint4*)(d_lwl + g);
        }
        __syncthreads();

        #pragma unroll 2
        for (int ks = 0; ks < 8; ks++) {
            uint32_t aH[2][4], aL[2][4], bH[4][4], bL[4][4];
            uint32_t ab = aoff + ks * 32;
            ldsm4(aH[0], ab);
            ldsm4(aH[1], ab + MSTEP);
            ldsm4(aL[0], ab + DA);
            ldsm4(aL[1], ab + DA + MSTEP);
            uint32_t bb = boff + ks * MSTEP;
            #pragma unroll
            for (int c = 0; c < 4; c++) {
                ldsm4t(bH[c], bb + c * 32);
                ldsm4t(bL[c], bb + c * 32 + DB);
            }
            #pragma unroll
            for (int mt = 0; mt < 2; mt++) {
                #pragma unroll
                for (int nc = 0; nc < 8; nc++) {
                    const uint32_t* bh = &bH[nc >> 1][(nc & 1) << 1];
                    const uint32_t* bl = &bL[nc >> 1][(nc & 1) << 1];
                    mma16816(acc[mt][nc], aH[mt], bh);
                    mma16816(acc[mt][nc], aH[mt], bl);
                    mma16816(acc[mt][nc], aL[mt], bh);
                }
            }
        }
        __syncthreads();
    }

    // ---- epilogue: acc (+bias) -> T, transpose, add residual, write d_out ----
    float* T = (float*)(dynsm + 69632);   // 128 x 129 floats, reuses B region
    const int r = lane >> 2, cq = (lane & 3) << 1;
    #pragma unroll
    for (int mt = 0; mt < 2; mt++) {
        int row0 = m0w + mt * 16 + r;     // w4
        int row1 = row0 + 8;
        #pragma unroll
        for (int nc = 0; nc < 8; nc++) {
            int lc = n0w + nc * 8 + cq;   // h4
            float* a4 = acc[mt][nc];
            float b0 = lb[lc], b1 = lb[lc + 1];
            T[row0 * 129 + lc]     = a4[0] + b0;
            T[row0 * 129 + lc + 1] = a4[1] + b1;
            T[row1 * 129 + lc]     = a4[2] + b0;
            T[row1 * 129 + lc + 1] = a4[3] + b1;
        }
    }
    __syncthreads();

    const size_t obase = ((size_t)(b * 128 + c4)) << 14;   // *16384
    #pragma unroll 8
    for (int it = 0; it < 64; it++) {
        int idx = tid + (it << 8);        // = h4*128 + w4
        int h4 = idx >> 7, w4 = idx & 127;
        float v = T[w4 * 129 + h4];
        out[obase + idx] = v + Fi[obase + idx] + Fw[obase + idx];
    }
}

// ---------------------------------------------------------------------------
// Launch.  Inputs in setup_inputs() dict order (guard on in_sizes[5]).
// ---------------------------------------------------------------------------
extern "C" void kernel_launch(void* const* d_in, const int* in_sizes, int n_in,
                              void* d_out, int out_size) {
    (void)n_in; (void)out_size;
    const float* F_i = (const float*)d_in[0];
    const float* F_w = (const float*)d_in[1];

    const bool interleaved = (in_sizes[5] == 128);

    PtrArgs pa;
    pa.f[0] = F_i;
    pa.f[1] = F_w;
    pa.g[0] = (const float*)d_in[2];
    pa.g[1] = (const float*)d_in[3];

    int w_idx[6], b_idx[6], dw_idx[6], db_idx[6];
    if (interleaved) {
        for (int t = 0; t < 6; t++) {
            w_idx[t]  = 4 + 2 * t;
            b_idx[t]  = 5 + 2 * t;
            dw_idx[t] = 16 + 2 * t;
            db_idx[t] = 17 + 2 * t;
        }
    } else {
        for (int t = 0; t < 6; t++) {
            w_idx[t]  = 4 + t;
            b_idx[t]  = 10 + t;
            dw_idx[t] = 16 + t;
            db_idx[t] = 22 + t;
        }
    }
    DwArgs da;
    for (int t = 0; t < 6; t++) {
        pa.w[t]    = (const float*)d_in[w_idx[t]];
        pa.bias[t] = (const float*)d_in[b_idx[t]];
        da.w[t]    = (const float*)d_in[dw_idx[t]];
        da.b[t]    = (const float*)d_in[db_idx[t]];
    }

    cudaFuncSetAttribute(k_conv, cudaFuncAttributeMaxDynamicSharedMemorySize, SMTOT2);
    cudaFuncSetAttribute(k_av, cudaFuncAttributeMaxDynamicSharedMemorySize, SMTOT2);
    cudaFuncSetAttribute(k_final3, cudaFuncAttributeMaxDynamicSharedMemorySize, SMTOT2);

    // 0) weight*gamma (split planes) + row sums; lw transpose+split
    k_prep<<<6 * 128, 128>>>(pa);
    k_prepLW<<<256, 128>>>((const float*)d_in[28]);
    // 1) LN stats
    k_ln<<<dim3(BATCH * HWX / 256, 2), 256>>>(pa);
    // 2) fused LN + 1x1 conv on HMMA (pipelined, 4 tiles/CTA)
    k_conv<<<dim3(48, 32), 256, SMTOT2>>>(pa);
    // 3) depthwise 3x3 (writes split planes)
    k_dw2<<<dim3(4, 6144), dim3(32, 4)>>>(da);
    // 4) QK logits split-K on HMMA (9 slabs, 1 wave)
    k_qk3<<<dim3(9, 16), 256>>>();
    // 5) reduce + softmax (writes split probs planes)
    k_softmax<<<2048, 128>>>();
    // 6) AV GEMMs on HMMA (pipelined; split-plane fills + split epilogue)
    k_av<<<dim3(16, 32), 256, SMTOT2>>>();
    // 7) final linear + permutation + residual (writes d_out directly)
    k_final3<<<dim3(128, 8), 256, SMTOT2>>>((const float*)d_in[29],
                                            F_i, F_w, (float*)d_out);
}